// round 2
// baseline (speedup 1.0000x reference)
#include <cuda_runtime.h>
#include <cstdint>

// Problem constants
#define NB 4
#define TT 4096
#define CC 512
#define KD 64           // key/value dim
#define BM 64           // queries per flash unit
#define CHUNK 512       // keys per flash unit (split-K)
#define SK 64           // key subtile staged in smem
#define QT (TT/BM)      // 64 query tiles per batch
#define NCH (TT/CHUNK)  // 8 key chunks per batch
#define GROUP 16        // online-softmax group size
#define OUTC 576        // 512 + 64

// q scale folded in: (1/sqrt(64)) * log2(e)  -> softmax computed in exp2 domain
#define QS 0.1803368801111244f

// ------------------------- scratch (device globals; no allocs) -------------
__device__ float g_q[NB * TT * KD];                 // 4 MB
__device__ float g_k[NB * TT * KD];                 // 4 MB
__device__ float g_v[NB * TT * KD];                 // 4 MB
__device__ float g_po[(size_t)NB * QT * NCH * BM * KD];  // 33.5 MB partial O
__device__ float g_pm[NB * QT * NCH * BM];          // partial max (exp2 domain)
__device__ float g_pl[NB * QT * NCH * BM];          // partial sum

// ------------------------- f32x2 helpers -----------------------------------
__device__ __forceinline__ unsigned long long ffma2(unsigned long long a,
                                                    unsigned long long b,
                                                    unsigned long long c) {
    unsigned long long d;
    asm("fma.rn.f32x2 %0, %1, %2, %3;" : "=l"(d) : "l"(a), "l"(b), "l"(c));
    return d;
}
__device__ __forceinline__ unsigned long long fmul2(unsigned long long a,
                                                    unsigned long long b) {
    unsigned long long d;
    asm("mul.rn.f32x2 %0, %1, %2;" : "=l"(d) : "l"(a), "l"(b));
    return d;
}
__device__ __forceinline__ unsigned long long pack2(float lo, float hi) {
    unsigned long long d;
    asm("mov.b64 %0, {%1, %2};" : "=l"(d) : "f"(lo), "f"(hi));
    return d;
}
__device__ __forceinline__ float2 unpack2(unsigned long long v) {
    float2 r;
    asm("mov.b64 {%0, %1}, %2;" : "=f"(r.x), "=f"(r.y) : "l"(v));
    return r;
}
__device__ __forceinline__ float ex2f(float x) {
    float r;
    asm("ex2.approx.f32 %0, %1;" : "=f"(r) : "f"(x));
    return r;
}

// ------------------------- QKV projection GEMM ------------------------------
// out[M=16384, 64] = x[M, 512] @ W[512, 64] + bias, optionally * scale.
// Block: 256 threads, tile 64 rows x 64 cols, K chunks of 16.
__global__ __launch_bounds__(256) void qkv_kernel(
    const float* __restrict__ x, const float* __restrict__ W,
    const float* __restrict__ bias, int which, float scale) {
    float* outp = (which == 0) ? g_q : (which == 1) ? g_k : g_v;

    const int row0 = blockIdx.x * 64;
    const int tid = threadIdx.x;
    const int tx = tid & 15;   // -> 4 output cols  c0 = tx*4
    const int ty = tid >> 4;   // -> 4 output rows  r0 = ty*4
    const int c0 = tx * 4;

    __shared__ float xs[16][68];   // [kk][row], padded
    __shared__ float ws[16][64];   // [kk][col]

    unsigned long long acc2[4][2];
#pragma unroll
    for (int i = 0; i < 4; i++) { acc2[i][0] = 0ULL; acc2[i][1] = 0ULL; }

    // staging indices
    const int xrow = tid >> 2;       // 0..63
    const int xkq  = tid & 3;        // 0..3 (quad of k)
    const int wkk  = tid >> 4;       // 0..15
    const int wcq  = tid & 15;       // 0..15

    for (int k0 = 0; k0 < CC; k0 += 16) {
        __syncthreads();
        {
            float4 xv = ((const float4*)x)[(size_t)(row0 + xrow) * (CC / 4) + (k0 >> 2) + xkq];
            xs[xkq * 4 + 0][xrow] = xv.x;
            xs[xkq * 4 + 1][xrow] = xv.y;
            xs[xkq * 4 + 2][xrow] = xv.z;
            xs[xkq * 4 + 3][xrow] = xv.w;
            float4 wv = ((const float4*)W)[(size_t)(k0 + wkk) * (KD / 4) + wcq];
            *(float4*)&ws[wkk][wcq * 4] = wv;
        }
        __syncthreads();
#pragma unroll
        for (int kk = 0; kk < 16; kk++) {
            const unsigned long long* bp =
                (const unsigned long long*)&ws[kk][c0];
            unsigned long long b0 = bp[0], b1 = bp[1];
            float4 av = *(const float4*)&xs[kk][ty * 4];
            unsigned long long a0 = pack2(av.x, av.x);
            unsigned long long a1 = pack2(av.y, av.y);
            unsigned long long a2 = pack2(av.z, av.z);
            unsigned long long a3 = pack2(av.w, av.w);
            acc2[0][0] = ffma2(a0, b0, acc2[0][0]);
            acc2[0][1] = ffma2(a0, b1, acc2[0][1]);
            acc2[1][0] = ffma2(a1, b0, acc2[1][0]);
            acc2[1][1] = ffma2(a1, b1, acc2[1][1]);
            acc2[2][0] = ffma2(a2, b0, acc2[2][0]);
            acc2[2][1] = ffma2(a2, b1, acc2[2][1]);
            acc2[3][0] = ffma2(a3, b0, acc2[3][0]);
            acc2[3][1] = ffma2(a3, b1, acc2[3][1]);
        }
    }

    float4 bv = ((const float4*)bias)[tx];
#pragma unroll
    for (int i = 0; i < 4; i++) {
        float2 p0 = unpack2(acc2[i][0]);
        float2 p1 = unpack2(acc2[i][1]);
        float4 r;
        r.x = (p0.x + bv.x) * scale;
        r.y = (p0.y + bv.y) * scale;
        r.z = (p1.x + bv.z) * scale;
        r.w = (p1.y + bv.w) * scale;
        int row = row0 + ty * 4 + i;
        ((float4*)outp)[(size_t)row * (KD / 4) + tx] = r;
    }
}

// ------------------------- x -> out[:, :512] copy ---------------------------
__global__ __launch_bounds__(128) void xcopy_kernel(const float4* __restrict__ x4,
                                                    float4* __restrict__ out4) {
    size_t row = blockIdx.x;
    int c = threadIdx.x;  // 0..127
    out4[row * (OUTC / 4) + c] = x4[row * (CC / 4) + c];
}

// ------------------------- flash partial (split-K) --------------------------
// grid (NCH, QT, NB); block 64 threads, 1 query per thread.
// q pre-scaled by QS -> logits already in exp2 domain.
__global__ __launch_bounds__(64) void flash_partial() {
    const int c = blockIdx.x;
    const int qt = blockIdx.y;
    const int b = blockIdx.z;
    const int qend = (qt + 1) * BM;       // exclusive key bound for this tile
    const int k0 = c * CHUNK;
    if (k0 >= qend) return;               // chunk entirely above diagonal
    const int kend = (k0 + CHUNK < qend) ? (k0 + CHUNK) : qend;

    const int tid = threadIdx.x;
    const int tq = qt * BM + tid;         // this thread's query position

    __shared__ float ks[SK][KD];
    __shared__ float vs[SK][KD];

    // load q row into registers as 32 packed f32x2
    unsigned long long q2[32];
    {
        const ulonglong2* qp =
            (const ulonglong2*)(g_q + ((size_t)b * TT + tq) * KD);
#pragma unroll
        for (int i = 0; i < 16; i++) {
            ulonglong2 u = qp[i];
            q2[2 * i] = u.x;
            q2[2 * i + 1] = u.y;
        }
    }

    unsigned long long o2[32];
#pragma unroll
    for (int i = 0; i < 32; i++) o2[i] = 0ULL;
    float m = -1e30f, l = 0.f;

    for (int s0 = k0; s0 < kend; s0 += SK) {
        __syncthreads();
        {
            const float4* kp = (const float4*)(g_k + ((size_t)b * TT + s0) * KD);
            const float4* vp = (const float4*)(g_v + ((size_t)b * TT + s0) * KD);
#pragma unroll
            for (int it = 0; it < 16; it++) {
                int idx = it * 64 + tid;          // 0..1023 float4s
                ((float4*)ks)[idx] = kp[idx];
                ((float4*)vs)[idx] = vp[idx];
            }
        }
        __syncthreads();

#pragma unroll 1
        for (int g = 0; g < SK / GROUP; g++) {
            const int jb = g * GROUP;
            float s[GROUP];
#pragma unroll
            for (int u = 0; u < GROUP; u++) {
                const unsigned long long* kr =
                    (const unsigned long long*)&ks[jb + u][0];
                unsigned long long accA = 0ULL, accB = 0ULL;
#pragma unroll
                for (int d = 0; d < 32; d += 2) {
                    accA = ffma2(q2[d], kr[d], accA);
                    accB = ffma2(q2[d + 1], kr[d + 1], accB);
                }
                float2 pa = unpack2(accA), pb = unpack2(accB);
                float sv = (pa.x + pa.y) + (pb.x + pb.y);
                int jg = s0 + jb + u;
                s[u] = (jg <= tq) ? sv : -1e30f;
            }
            float gm = s[0];
#pragma unroll
            for (int u = 1; u < GROUP; u++) gm = fmaxf(gm, s[u]);
            float mn = fmaxf(m, gm);
            float corr = ex2f(m - mn);  // 1 if unchanged; 0 on first real group
            m = mn;
            l *= corr;
            unsigned long long c2 = pack2(corr, corr);
#pragma unroll
            for (int d = 0; d < 32; d++) o2[d] = fmul2(o2[d], c2);
#pragma unroll
            for (int u = 0; u < GROUP; u++) {
                int jg = s0 + jb + u;
                float p = (jg <= tq) ? ex2f(s[u] - m) : 0.f;
                l += p;
                unsigned long long p2 = pack2(p, p);
                const unsigned long long* vr =
                    (const unsigned long long*)&vs[jb + u][0];
#pragma unroll
                for (int d = 0; d < 32; d++) o2[d] = ffma2(p2, vr[d], o2[d]);
            }
        }
    }

    // write partials
    const size_t unit = ((size_t)(b * QT + qt) * NCH + c);
    g_pm[unit * BM + tid] = m;
    g_pl[unit * BM + tid] = l;
    float4* po = (float4*)(g_po + (unit * BM + tid) * KD);
#pragma unroll
    for (int i = 0; i < 16; i++) {
        float2 a = unpack2(o2[2 * i]);
        float2 bb = unpack2(o2[2 * i + 1]);
        po[i] = make_float4(a.x, a.y, bb.x, bb.y);
    }
}

// ------------------------- merge partials -> out[:, 512:576] ----------------
// block (64, 4): threadIdx.x = dim, threadIdx.y = query within block of 4.
__global__ __launch_bounds__(256) void merge_kernel(float* __restrict__ out) {
    const int d = threadIdx.x;
    const int qg = blockIdx.x * 4 + threadIdx.y;   // 0..16383
    const int b = qg / TT;
    const int t = qg % TT;
    const int qt = t / BM;
    const int qloc = t % BM;
    const int nc = t / CHUNK + 1;
    const size_t base = (size_t)(b * QT + qt) * NCH;

    float M = -1e30f;
#pragma unroll 1
    for (int c = 0; c < nc; c++)
        M = fmaxf(M, g_pm[(base + c) * BM + qloc]);

    float L = 0.f, acc = 0.f;
#pragma unroll 1
    for (int c = 0; c < nc; c++) {
        float w = ex2f(g_pm[(base + c) * BM + qloc] - M);
        L += w * g_pl[(base + c) * BM + qloc];
        acc += w * g_po[((base + c) * BM + qloc) * KD + d];
    }
    out[(size_t)qg * OUTC + CC + d] = acc / L;
}

// ------------------------- launch -------------------------------------------
extern "C" void kernel_launch(void* const* d_in, const int* in_sizes, int n_in,
                              void* d_out, int out_size) {
    (void)in_sizes; (void)n_in; (void)out_size;
    const float* x  = (const float*)d_in[0];
    const float* Wq = (const float*)d_in[1];
    const float* bq = (const float*)d_in[2];
    const float* Wk = (const float*)d_in[3];
    const float* bk = (const float*)d_in[4];
    const float* Wv = (const float*)d_in[5];
    const float* bv = (const float*)d_in[6];
    float* out = (float*)d_out;

    const int M = NB * TT;  // 16384 rows

    qkv_kernel<<<M / 64, 256>>>(x, Wq, bq, 0, QS);
    qkv_kernel<<<M / 64, 256>>>(x, Wk, bk, 1, 1.0f);
    qkv_kernel<<<M / 64, 256>>>(x, Wv, bv, 2, 1.0f);
    xcopy_kernel<<<M, 128>>>((const float4*)x, (float4*)out);
    flash_partial<<<dim3(NCH, QT, NB), BM>>>();
    merge_kernel<<<M / 4, dim3(64, 4)>>>(out);
}

// round 3
// speedup vs baseline: 3.2820x; 3.2820x over previous
#include <cuda_runtime.h>
#include <cstdint>

typedef unsigned long long ull;

// Problem constants
#define NB 4
#define TT 4096
#define CC 512
#define KD 64           // key/value dim
#define BM 64           // queries per flash unit
#define CHUNK 512       // keys per flash unit (split-K)
#define QT (TT/BM)      // 64 query tiles per batch
#define NCH (TT/CHUNK)  // 8 key chunks per batch
#define OUTC 576        // 512 + 64

// q scale folded in: (1/sqrt(64)) * log2(e)  -> softmax computed in exp2 domain
#define QS 0.1803368801111244f

// ------------------------- scratch (device globals; no allocs) -------------
__device__ float g_q[NB * TT * KD];                 // 4 MB
__device__ float g_k[NB * TT * KD];                 // 4 MB
__device__ float g_v[NB * TT * KD];                 // 4 MB
__device__ float g_po[(size_t)NB * QT * NCH * BM * KD];  // 33.5 MB partial O
__device__ float g_pm[NB * QT * NCH * BM];          // partial max (exp2 domain)
__device__ float g_pl[NB * QT * NCH * BM];          // partial sum

// ------------------------- f32x2 helpers -----------------------------------
__device__ __forceinline__ ull ffma2(ull a, ull b, ull c) {
    ull d;
    asm("fma.rn.f32x2 %0, %1, %2, %3;" : "=l"(d) : "l"(a), "l"(b), "l"(c));
    return d;
}
__device__ __forceinline__ ull fmul2(ull a, ull b) {
    ull d;
    asm("mul.rn.f32x2 %0, %1, %2;" : "=l"(d) : "l"(a), "l"(b));
    return d;
}
__device__ __forceinline__ ull pack2(float lo, float hi) {
    ull d;
    asm("mov.b64 %0, {%1, %2};" : "=l"(d) : "f"(lo), "f"(hi));
    return d;
}
__device__ __forceinline__ float2 unpack2(ull v) {
    float2 r;
    asm("mov.b64 {%0, %1}, %2;" : "=f"(r.x), "=f"(r.y) : "l"(v));
    return r;
}
__device__ __forceinline__ float ex2f(float x) {
    float r;
    asm("ex2.approx.f32 %0, %1;" : "=f"(r) : "f"(x));
    return r;
}

// ------------------------- QKV projection GEMM ------------------------------
__global__ __launch_bounds__(256) void qkv_kernel(
    const float* __restrict__ x, const float* __restrict__ W,
    const float* __restrict__ bias, int which, float scale) {
    float* outp = (which == 0) ? g_q : (which == 1) ? g_k : g_v;

    const int row0 = blockIdx.x * 64;
    const int tid = threadIdx.x;
    const int tx = tid & 15;   // -> 4 output cols  c0 = tx*4
    const int ty = tid >> 4;   // -> 4 output rows  r0 = ty*4
    const int c0 = tx * 4;

    __shared__ float xs[16][68];   // [kk][row], padded
    __shared__ float ws[16][64];   // [kk][col]

    ull acc2[4][2];
#pragma unroll
    for (int i = 0; i < 4; i++) { acc2[i][0] = 0ULL; acc2[i][1] = 0ULL; }

    const int xrow = tid >> 2;       // 0..63
    const int xkq  = tid & 3;        // 0..3 (quad of k)
    const int wkk  = tid >> 4;       // 0..15
    const int wcq  = tid & 15;       // 0..15

    for (int k0 = 0; k0 < CC; k0 += 16) {
        __syncthreads();
        {
            float4 xv = ((const float4*)x)[(size_t)(row0 + xrow) * (CC / 4) + (k0 >> 2) + xkq];
            xs[xkq * 4 + 0][xrow] = xv.x;
            xs[xkq * 4 + 1][xrow] = xv.y;
            xs[xkq * 4 + 2][xrow] = xv.z;
            xs[xkq * 4 + 3][xrow] = xv.w;
            float4 wv = ((const float4*)W)[(size_t)(k0 + wkk) * (KD / 4) + wcq];
            *(float4*)&ws[wkk][wcq * 4] = wv;
        }
        __syncthreads();
#pragma unroll
        for (int kk = 0; kk < 16; kk++) {
            const ull* bp = (const ull*)&ws[kk][c0];
            ull b0 = bp[0], b1 = bp[1];
            float4 av = *(const float4*)&xs[kk][ty * 4];
            ull a0 = pack2(av.x, av.x);
            ull a1 = pack2(av.y, av.y);
            ull a2 = pack2(av.z, av.z);
            ull a3 = pack2(av.w, av.w);
            acc2[0][0] = ffma2(a0, b0, acc2[0][0]);
            acc2[0][1] = ffma2(a0, b1, acc2[0][1]);
            acc2[1][0] = ffma2(a1, b0, acc2[1][0]);
            acc2[1][1] = ffma2(a1, b1, acc2[1][1]);
            acc2[2][0] = ffma2(a2, b0, acc2[2][0]);
            acc2[2][1] = ffma2(a2, b1, acc2[2][1]);
            acc2[3][0] = ffma2(a3, b0, acc2[3][0]);
            acc2[3][1] = ffma2(a3, b1, acc2[3][1]);
        }
    }

    float4 bv = ((const float4*)bias)[tx];
#pragma unroll
    for (int i = 0; i < 4; i++) {
        float2 p0 = unpack2(acc2[i][0]);
        float2 p1 = unpack2(acc2[i][1]);
        float4 r;
        r.x = (p0.x + bv.x) * scale;
        r.y = (p0.y + bv.y) * scale;
        r.z = (p1.x + bv.z) * scale;
        r.w = (p1.y + bv.w) * scale;
        int row = row0 + ty * 4 + i;
        ((float4*)outp)[(size_t)row * (KD / 4) + tx] = r;
    }
}

// ------------------------- x -> out[:, :512] copy ---------------------------
__global__ __launch_bounds__(128) void xcopy_kernel(const float4* __restrict__ x4,
                                                    float4* __restrict__ out4) {
    size_t row = blockIdx.x;
    int c = threadIdx.x;  // 0..127
    out4[row * (OUTC / 4) + c] = x4[row * (CC / 4) + c];
}

// ------------------------- flash partial (register-tiled, split-K) ----------
// grid (NCH, QT, NB); block 256 threads.
// Each block: 64 queries x 512-key chunk. Per 64-key subtile:
//   S = Q*K^T (reg 4x4 tiles), row softmax (16-lane shfl), P -> smem (swizzled
//   transposed), O += P*V (reg 4x4 tiles). Online rescale per subtile.
__global__ __launch_bounds__(256, 2) void flash_partial() {
    const int c = blockIdx.x;
    const int qt = blockIdx.y;
    const int b = blockIdx.z;
    const int qend = (qt + 1) * BM;
    const int k0 = c * CHUNK;
    if (k0 >= qend) return;
    const int kend = (k0 + CHUNK < qend) ? (k0 + CHUNK) : qend;
    const int diag_s0 = qend - 64;

    const int tid = threadIdx.x;
    const int tx = tid & 15;        // key/vdim group
    const int ty = tid >> 4;        // query group
    const int r0 = ty * 4;
    const int c0 = tx * 4;
    const int swz = tx & 7;

    __shared__ float qs[64 * 64];   // [q][d] plain (reads are broadcast)
    __shared__ float ks[64 * 64];   // [k][d] granule-swizzled
    __shared__ float vs[64 * 64];   // [k][v] plain
    __shared__ float ps[64 * 64];   // P^T [k][q] granule-swizzled

    // stage q tile (once)
    {
        const float4* qp = (const float4*)(g_q + ((size_t)b * TT + qt * BM) * KD);
#pragma unroll
        for (int i = 0; i < 4; i++) {
            int f = tid + i * 256;
            ((float4*)qs)[f] = qp[f];
        }
    }

    ull o2[4][2];
    float m[4], l[4];
#pragma unroll
    for (int i = 0; i < 4; i++) {
        o2[i][0] = 0ULL; o2[i][1] = 0ULL;
        m[i] = -1e30f; l[i] = 0.f;
    }

    for (int s0 = k0; s0 < kend; s0 += 64) {
        __syncthreads();   // prev PV done before overwriting ks/vs/ps
        {
            const float4* kp = (const float4*)(g_k + ((size_t)b * TT + s0) * KD);
            const float4* vp = (const float4*)(g_v + ((size_t)b * TT + s0) * KD);
#pragma unroll
            for (int i = 0; i < 4; i++) {
                int f = tid + i * 256;
                int row = f >> 4, dq = f & 15;
                float4 kv = kp[f];
                int g = dq ^ ((row >> 2) & 7);
                *(float4*)&ks[row * 64 + g * 4] = kv;
                ((float4*)vs)[f] = vp[f];
            }
        }
        __syncthreads();

        // ---- S = Q K^T ----
        ull sacc[4][4];
#pragma unroll
        for (int i = 0; i < 4; i++)
#pragma unroll
            for (int j = 0; j < 4; j++) sacc[i][j] = 0ULL;

#pragma unroll
        for (int d0 = 0; d0 < 64; d0 += 4) {
            ulonglong2 qa[4], kb[4];
#pragma unroll
            for (int i = 0; i < 4; i++)
                qa[i] = *(const ulonglong2*)&qs[(r0 + i) * 64 + d0];
#pragma unroll
            for (int j = 0; j < 4; j++)
                kb[j] = *(const ulonglong2*)&ks[(c0 + j) * 64 + (((d0 >> 2) ^ swz) << 2)];
#pragma unroll
            for (int i = 0; i < 4; i++)
#pragma unroll
                for (int j = 0; j < 4; j++) {
                    sacc[i][j] = ffma2(qa[i].x, kb[j].x, sacc[i][j]);
                    sacc[i][j] = ffma2(qa[i].y, kb[j].y, sacc[i][j]);
                }
        }

        const bool diag = (s0 == diag_s0);

        // ---- row softmax (online) ----
        float p[4][4];
#pragma unroll
        for (int i = 0; i < 4; i++) {
            float sv[4];
#pragma unroll
            for (int j = 0; j < 4; j++) {
                float2 t = unpack2(sacc[i][j]);
                float v = t.x + t.y;
                if (diag && (c0 + j > r0 + i)) v = -1e30f;
                sv[j] = v;
            }
            float mx = fmaxf(fmaxf(sv[0], sv[1]), fmaxf(sv[2], sv[3]));
#pragma unroll
            for (int off = 8; off >= 1; off >>= 1)
                mx = fmaxf(mx, __shfl_xor_sync(0xffffffffu, mx, off));
            float mn = fmaxf(m[i], mx);
            float corr = ex2f(m[i] - mn);
            m[i] = mn;
            float rs = 0.f;
#pragma unroll
            for (int j = 0; j < 4; j++) {
                p[i][j] = ex2f(sv[j] - mn);
                rs += p[i][j];
            }
#pragma unroll
            for (int off = 8; off >= 1; off >>= 1)
                rs += __shfl_xor_sync(0xffffffffu, rs, off);
            l[i] = l[i] * corr + rs;
            ull c2 = pack2(corr, corr);
            o2[i][0] = fmul2(o2[i][0], c2);
            o2[i][1] = fmul2(o2[i][1], c2);
        }

        // ---- write P^T (swizzled): ps[key][q] ----
        {
            int g4 = (ty ^ swz) << 2;
#pragma unroll
            for (int j = 0; j < 4; j++)
#pragma unroll
                for (int i = 0; i < 4; i++)
                    ps[(c0 + j) * 64 + g4 + i] = p[i][j];
        }
        __syncthreads();

        // ---- O += P V ----
#pragma unroll 8
        for (int kk = 0; kk < 64; kk++) {
            float4 pv = *(const float4*)&ps[kk * 64 + ((ty ^ ((kk >> 2) & 7)) << 2)];
            ulonglong2 vv = *(const ulonglong2*)&vs[kk * 64 + c0];
            ull p0 = pack2(pv.x, pv.x);
            ull p1 = pack2(pv.y, pv.y);
            ull p2 = pack2(pv.z, pv.z);
            ull p3 = pack2(pv.w, pv.w);
            o2[0][0] = ffma2(p0, vv.x, o2[0][0]);
            o2[0][1] = ffma2(p0, vv.y, o2[0][1]);
            o2[1][0] = ffma2(p1, vv.x, o2[1][0]);
            o2[1][1] = ffma2(p1, vv.y, o2[1][1]);
            o2[2][0] = ffma2(p2, vv.x, o2[2][0]);
            o2[2][1] = ffma2(p2, vv.y, o2[2][1]);
            o2[3][0] = ffma2(p3, vv.x, o2[3][0]);
            o2[3][1] = ffma2(p3, vv.y, o2[3][1]);
        }
    }

    // ---- write partials ----
    const size_t unit = ((size_t)(b * QT + qt) * NCH + c);
    if (tx == 0) {
#pragma unroll
        for (int i = 0; i < 4; i++) {
            g_pm[unit * BM + r0 + i] = m[i];
            g_pl[unit * BM + r0 + i] = l[i];
        }
    }
    float4* po = (float4*)(g_po + (unit * BM) * KD);
#pragma unroll
    for (int i = 0; i < 4; i++) {
        float2 a = unpack2(o2[i][0]);
        float2 bb = unpack2(o2[i][1]);
        po[(size_t)(r0 + i) * 16 + tx] = make_float4(a.x, a.y, bb.x, bb.y);
    }
}

// ------------------------- merge partials -> out[:, 512:576] ----------------
__global__ __launch_bounds__(256) void merge_kernel(float* __restrict__ out) {
    const int d = threadIdx.x;
    const int qg = blockIdx.x * 4 + threadIdx.y;   // 0..16383
    const int b = qg / TT;
    const int t = qg % TT;
    const int qt = t / BM;
    const int qloc = t % BM;
    const int nc = t / CHUNK + 1;
    const size_t base = (size_t)(b * QT + qt) * NCH;

    float M = -1e30f;
#pragma unroll 1
    for (int c = 0; c < nc; c++)
        M = fmaxf(M, g_pm[(base + c) * BM + qloc]);

    float L = 0.f, acc = 0.f;
#pragma unroll 1
    for (int c = 0; c < nc; c++) {
        float w = ex2f(g_pm[(base + c) * BM + qloc] - M);
        L += w * g_pl[(base + c) * BM + qloc];
        acc += w * g_po[((base + c) * BM + qloc) * KD + d];
    }
    out[(size_t)qg * OUTC + CC + d] = acc / L;
}

// ------------------------- launch -------------------------------------------
extern "C" void kernel_launch(void* const* d_in, const int* in_sizes, int n_in,
                              void* d_out, int out_size) {
    (void)in_sizes; (void)n_in; (void)out_size;
    const float* x  = (const float*)d_in[0];
    const float* Wq = (const float*)d_in[1];
    const float* bq = (const float*)d_in[2];
    const float* Wk = (const float*)d_in[3];
    const float* bk = (const float*)d_in[4];
    const float* Wv = (const float*)d_in[5];
    const float* bv = (const float*)d_in[6];
    float* out = (float*)d_out;

    const int M = NB * TT;  // 16384 rows

    qkv_kernel<<<M / 64, 256>>>(x, Wq, bq, 0, QS);
    qkv_kernel<<<M / 64, 256>>>(x, Wk, bk, 1, 1.0f);
    qkv_kernel<<<M / 64, 256>>>(x, Wv, bv, 2, 1.0f);
    xcopy_kernel<<<M, 128>>>((const float4*)x, (float4*)out);
    flash_partial<<<dim3(NCH, QT, NB), 256>>>();
    merge_kernel<<<M / 4, dim3(64, 4)>>>(out);
}

// round 4
// speedup vs baseline: 5.6241x; 1.7136x over previous
#include <cuda_runtime.h>
#include <cstdint>

typedef unsigned long long ull;

// Problem constants
#define NB 4
#define TT 4096
#define CC 512
#define KD 64           // key/value dim
#define BM 64           // queries per flash unit
#define CHUNK 512       // keys per flash unit (split-K)
#define QT (TT/BM)      // 64 query tiles per batch
#define NCH (TT/CHUNK)  // 8 key chunks per batch
#define OUTC 576        // 512 + 64

// q scale folded in: (1/sqrt(64)) * log2(e)  -> softmax computed in exp2 domain
#define QS 0.1803368801111244f

// smem strides (floats) chosen for conflict-free fragment access
#define SQ 68   // qs, ks, ps
#define SV 72   // vs
#define FLASH_SMEM_FLOATS (64*SQ*3 + 64*SV + 256)
#define FLASH_SMEM_BYTES (FLASH_SMEM_FLOATS * 4)

// ------------------------- scratch (device globals; no allocs) -------------
__device__ float g_q[NB * TT * KD];                 // 4 MB
__device__ float g_k[NB * TT * KD];                 // 4 MB
__device__ float g_v[NB * TT * KD];                 // 4 MB
__device__ float g_po[(size_t)NB * QT * NCH * BM * KD];  // 33.5 MB partial O
__device__ float g_pm[NB * QT * NCH * BM];          // partial max (exp2 domain)
__device__ float g_pl[NB * QT * NCH * BM];          // partial sum

// ------------------------- helpers -----------------------------------------
__device__ __forceinline__ ull ffma2(ull a, ull b, ull c) {
    ull d;
    asm("fma.rn.f32x2 %0, %1, %2, %3;" : "=l"(d) : "l"(a), "l"(b), "l"(c));
    return d;
}
__device__ __forceinline__ ull pack2(float lo, float hi) {
    ull d;
    asm("mov.b64 %0, {%1, %2};" : "=l"(d) : "f"(lo), "f"(hi));
    return d;
}
__device__ __forceinline__ float2 unpack2(ull v) {
    float2 r;
    asm("mov.b64 {%0, %1}, %2;" : "=f"(r.x), "=f"(r.y) : "l"(v));
    return r;
}
__device__ __forceinline__ float ex2f(float x) {
    float r;
    asm("ex2.approx.f32 %0, %1;" : "=f"(r) : "f"(x));
    return r;
}
__device__ __forceinline__ void mma_tf32(float& d0, float& d1, float& d2, float& d3,
                                         unsigned a0, unsigned a1, unsigned a2, unsigned a3,
                                         unsigned b0, unsigned b1) {
    asm volatile(
        "mma.sync.aligned.m16n8k8.row.col.f32.tf32.tf32.f32 "
        "{%0,%1,%2,%3}, {%4,%5,%6,%7}, {%8,%9}, {%0,%1,%2,%3};"
        : "+f"(d0), "+f"(d1), "+f"(d2), "+f"(d3)
        : "r"(a0), "r"(a1), "r"(a2), "r"(a3), "r"(b0), "r"(b1));
}
#define F2U __float_as_uint

// ------------------------- fused QKV projection GEMM ------------------------
// grid (256, 3): blockIdx.y selects q/k/v. out[16384,64] = x @ W + b (q scaled)
__global__ __launch_bounds__(256) void qkv_kernel(
    const float* __restrict__ x,
    const float* __restrict__ Wq, const float* __restrict__ bq,
    const float* __restrict__ Wk, const float* __restrict__ bk,
    const float* __restrict__ Wv, const float* __restrict__ bv) {
    const int which = blockIdx.y;
    const float* W = (which == 0) ? Wq : (which == 1) ? Wk : Wv;
    const float* bias = (which == 0) ? bq : (which == 1) ? bk : bv;
    float* outp = (which == 0) ? g_q : (which == 1) ? g_k : g_v;
    const float scale = (which == 0) ? QS : 1.0f;

    const int row0 = blockIdx.x * 64;
    const int tid = threadIdx.x;
    const int tx = tid & 15;
    const int ty = tid >> 4;
    const int c0 = tx * 4;

    __shared__ float xs[16][68];
    __shared__ float ws[16][64];

    ull acc2[4][2];
#pragma unroll
    for (int i = 0; i < 4; i++) { acc2[i][0] = 0ULL; acc2[i][1] = 0ULL; }

    const int xrow = tid >> 2;
    const int xkq  = tid & 3;
    const int wkk  = tid >> 4;
    const int wcq  = tid & 15;

    for (int k0 = 0; k0 < CC; k0 += 16) {
        __syncthreads();
        {
            float4 xv = ((const float4*)x)[(size_t)(row0 + xrow) * (CC / 4) + (k0 >> 2) + xkq];
            xs[xkq * 4 + 0][xrow] = xv.x;
            xs[xkq * 4 + 1][xrow] = xv.y;
            xs[xkq * 4 + 2][xrow] = xv.z;
            xs[xkq * 4 + 3][xrow] = xv.w;
            float4 wv = ((const float4*)W)[(size_t)(k0 + wkk) * (KD / 4) + wcq];
            *(float4*)&ws[wkk][wcq * 4] = wv;
        }
        __syncthreads();
#pragma unroll
        for (int kk = 0; kk < 16; kk++) {
            const ull* bp = (const ull*)&ws[kk][c0];
            ull b0 = bp[0], b1 = bp[1];
            float4 av = *(const float4*)&xs[kk][ty * 4];
            ull a0 = pack2(av.x, av.x);
            ull a1 = pack2(av.y, av.y);
            ull a2 = pack2(av.z, av.z);
            ull a3 = pack2(av.w, av.w);
            acc2[0][0] = ffma2(a0, b0, acc2[0][0]);
            acc2[0][1] = ffma2(a0, b1, acc2[0][1]);
            acc2[1][0] = ffma2(a1, b0, acc2[1][0]);
            acc2[1][1] = ffma2(a1, b1, acc2[1][1]);
            acc2[2][0] = ffma2(a2, b0, acc2[2][0]);
            acc2[2][1] = ffma2(a2, b1, acc2[2][1]);
            acc2[3][0] = ffma2(a3, b0, acc2[3][0]);
            acc2[3][1] = ffma2(a3, b1, acc2[3][1]);
        }
    }

    float4 bv4 = ((const float4*)bias)[tx];
#pragma unroll
    for (int i = 0; i < 4; i++) {
        float2 p0 = unpack2(acc2[i][0]);
        float2 p1 = unpack2(acc2[i][1]);
        float4 r;
        r.x = (p0.x + bv4.x) * scale;
        r.y = (p0.y + bv4.y) * scale;
        r.z = (p1.x + bv4.z) * scale;
        r.w = (p1.y + bv4.w) * scale;
        int row = row0 + ty * 4 + i;
        ((float4*)outp)[(size_t)row * (KD / 4) + tx] = r;
    }
}

// ------------------------- x -> out[:, :512] copy ---------------------------
__global__ __launch_bounds__(128) void xcopy_kernel(const float4* __restrict__ x4,
                                                    float4* __restrict__ out4) {
    size_t row = blockIdx.x;
    int c = threadIdx.x;
    out4[row * (OUTC / 4) + c] = x4[row * (CC / 4) + c];
}

// ------------------------- flash partial (tf32 mma, split-K) ----------------
// grid (NCH, QT, NB); 256 threads = 8 warps.
// Warp w: rows 16*(w>>1), cols 32*(w&1) of the 64x64 S / O tiles.
__global__ __launch_bounds__(256) void flash_partial() {
    extern __shared__ float sm[];
    float* qs   = sm;                 // [64][SQ]
    float* ks   = qs + 64 * SQ;       // [64][SQ]
    float* ps   = ks + 64 * SQ;       // [64][SQ]  P (q x key)
    float* vs   = ps + 64 * SQ;       // [64][SV]
    float* redm = vs + 64 * SV;       // [64][2]
    float* reds = redm + 128;         // [64][2]

    const int c = blockIdx.x;
    const int qt = blockIdx.y;
    const int b = blockIdx.z;
    const int qend = (qt + 1) * BM;
    const int k0 = c * CHUNK;
    if (k0 >= qend) return;
    const int kend = (k0 + CHUNK < qend) ? (k0 + CHUNK) : qend;
    const int diag_s0 = qend - 64;

    const int tid = threadIdx.x;
    const int lane = tid & 31;
    const int warp = tid >> 5;
    const int rowblk = warp >> 1;
    const int colblk = warp & 1;
    const int r0 = rowblk * 16;
    const int n0base = colblk * 32;
    const int gid = lane >> 2;       // 0..7
    const int tig = lane & 3;        // 0..3

    // stage Q tile (once): [64 q][64 d] -> qs stride SQ
    {
        const float4* qp = (const float4*)(g_q + ((size_t)b * TT + qt * BM) * KD);
#pragma unroll
        for (int i = 0; i < 4; i++) {
            int f = tid + i * 256;
            int row = f >> 4, c4 = (f & 15) * 4;
            *(float4*)&qs[row * SQ + c4] = qp[f];
        }
    }

    float o[4][4];
#pragma unroll
    for (int nt = 0; nt < 4; nt++)
#pragma unroll
        for (int r = 0; r < 4; r++) o[nt][r] = 0.f;
    float m0 = -1e30f, m1 = -1e30f, l0 = 0.f, l1 = 0.f;

    for (int s0 = k0; s0 < kend; s0 += 64) {
        __syncthreads();
        {
            const float4* kp = (const float4*)(g_k + ((size_t)b * TT + s0) * KD);
            const float4* vp = (const float4*)(g_v + ((size_t)b * TT + s0) * KD);
#pragma unroll
            for (int i = 0; i < 4; i++) {
                int f = tid + i * 256;
                int row = f >> 4, c4 = (f & 15) * 4;
                *(float4*)&ks[row * SQ + c4] = kp[f];
                *(float4*)&vs[row * SV + c4] = vp[f];
            }
        }
        __syncthreads();

        // ---- S = Q K^T  (tf32 mma) ----
        float sacc[4][4];
#pragma unroll
        for (int nt = 0; nt < 4; nt++)
#pragma unroll
            for (int r = 0; r < 4; r++) sacc[nt][r] = 0.f;

#pragma unroll
        for (int k8 = 0; k8 < 8; k8++) {
            const int ca = k8 * 8 + tig;
            unsigned a0 = F2U(qs[(r0 + gid) * SQ + ca]);
            unsigned a1 = F2U(qs[(r0 + gid + 8) * SQ + ca]);
            unsigned a2 = F2U(qs[(r0 + gid) * SQ + ca + 4]);
            unsigned a3 = F2U(qs[(r0 + gid + 8) * SQ + ca + 4]);
#pragma unroll
            for (int nt = 0; nt < 4; nt++) {
                int key = n0base + nt * 8 + gid;
                unsigned b0 = F2U(ks[key * SQ + ca]);
                unsigned b1 = F2U(ks[key * SQ + ca + 4]);
                mma_tf32(sacc[nt][0], sacc[nt][1], sacc[nt][2], sacc[nt][3],
                         a0, a1, a2, a3, b0, b1);
            }
        }

        // ---- causal mask on diagonal subtile ----
        if (s0 == diag_s0) {
            const int rq0 = r0 + gid, rq1 = r0 + gid + 8;
#pragma unroll
            for (int nt = 0; nt < 4; nt++) {
                int ck = n0base + nt * 8 + 2 * tig;
                if (ck > rq0) sacc[nt][0] = -1e30f;
                if (ck + 1 > rq0) sacc[nt][1] = -1e30f;
                if (ck > rq1) sacc[nt][2] = -1e30f;
                if (ck + 1 > rq1) sacc[nt][3] = -1e30f;
            }
        }

        // ---- online softmax: cross-warp row max ----
        float mx0 = -1e30f, mx1 = -1e30f;
#pragma unroll
        for (int nt = 0; nt < 4; nt++) {
            mx0 = fmaxf(mx0, fmaxf(sacc[nt][0], sacc[nt][1]));
            mx1 = fmaxf(mx1, fmaxf(sacc[nt][2], sacc[nt][3]));
        }
        mx0 = fmaxf(mx0, __shfl_xor_sync(0xffffffffu, mx0, 1));
        mx0 = fmaxf(mx0, __shfl_xor_sync(0xffffffffu, mx0, 2));
        mx1 = fmaxf(mx1, __shfl_xor_sync(0xffffffffu, mx1, 1));
        mx1 = fmaxf(mx1, __shfl_xor_sync(0xffffffffu, mx1, 2));
        if (tig == 0) {
            redm[(r0 + gid) * 2 + colblk] = mx0;
            redm[(r0 + gid + 8) * 2 + colblk] = mx1;
        }
        __syncthreads();
        float mn0 = fmaxf(m0, fmaxf(redm[(r0 + gid) * 2], redm[(r0 + gid) * 2 + 1]));
        float mn1 = fmaxf(m1, fmaxf(redm[(r0 + gid + 8) * 2], redm[(r0 + gid + 8) * 2 + 1]));
        float corr0 = ex2f(m0 - mn0);
        float corr1 = ex2f(m1 - mn1);
        m0 = mn0; m1 = mn1;

        // ---- p = exp2(s - m), store P to smem, partial row sums ----
        float sum0 = 0.f, sum1 = 0.f;
#pragma unroll
        for (int nt = 0; nt < 4; nt++) {
            float p0 = ex2f(sacc[nt][0] - mn0);
            float p1 = ex2f(sacc[nt][1] - mn0);
            float p2 = ex2f(sacc[nt][2] - mn1);
            float p3 = ex2f(sacc[nt][3] - mn1);
            sum0 += p0 + p1;
            sum1 += p2 + p3;
            int ck = n0base + nt * 8 + 2 * tig;
            *(float2*)&ps[(r0 + gid) * SQ + ck] = make_float2(p0, p1);
            *(float2*)&ps[(r0 + gid + 8) * SQ + ck] = make_float2(p2, p3);
        }
        sum0 += __shfl_xor_sync(0xffffffffu, sum0, 1);
        sum0 += __shfl_xor_sync(0xffffffffu, sum0, 2);
        sum1 += __shfl_xor_sync(0xffffffffu, sum1, 1);
        sum1 += __shfl_xor_sync(0xffffffffu, sum1, 2);
        if (tig == 0) {
            reds[(r0 + gid) * 2 + colblk] = sum0;
            reds[(r0 + gid + 8) * 2 + colblk] = sum1;
        }
        __syncthreads();
        l0 = l0 * corr0 + reds[(r0 + gid) * 2] + reds[(r0 + gid) * 2 + 1];
        l1 = l1 * corr1 + reds[(r0 + gid + 8) * 2] + reds[(r0 + gid + 8) * 2 + 1];

        // ---- rescale O, then O += P V (tf32 mma) ----
#pragma unroll
        for (int nt = 0; nt < 4; nt++) {
            o[nt][0] *= corr0; o[nt][1] *= corr0;
            o[nt][2] *= corr1; o[nt][3] *= corr1;
        }
#pragma unroll
        for (int k8 = 0; k8 < 8; k8++) {
            const int ca = k8 * 8 + tig;
            unsigned a0 = F2U(ps[(r0 + gid) * SQ + ca]);
            unsigned a1 = F2U(ps[(r0 + gid + 8) * SQ + ca]);
            unsigned a2 = F2U(ps[(r0 + gid) * SQ + ca + 4]);
            unsigned a3 = F2U(ps[(r0 + gid + 8) * SQ + ca + 4]);
#pragma unroll
            for (int nt = 0; nt < 4; nt++) {
                int vc = n0base + nt * 8 + gid;
                unsigned b0 = F2U(vs[(k8 * 8 + tig) * SV + vc]);
                unsigned b1 = F2U(vs[(k8 * 8 + tig + 4) * SV + vc]);
                mma_tf32(o[nt][0], o[nt][1], o[nt][2], o[nt][3],
                         a0, a1, a2, a3, b0, b1);
            }
        }
    }

    // ---- write partials ----
    const size_t unit = ((size_t)(b * QT + qt) * NCH + c);
    if (colblk == 0 && tig == 0) {
        g_pm[unit * BM + r0 + gid] = m0;
        g_pm[unit * BM + r0 + gid + 8] = m1;
        g_pl[unit * BM + r0 + gid] = l0;
        g_pl[unit * BM + r0 + gid + 8] = l1;
    }
    float* po = g_po + unit * BM * KD;
#pragma unroll
    for (int nt = 0; nt < 4; nt++) {
        int ck = n0base + nt * 8 + 2 * tig;
        *(float2*)&po[(size_t)(r0 + gid) * KD + ck] = make_float2(o[nt][0], o[nt][1]);
        *(float2*)&po[(size_t)(r0 + gid + 8) * KD + ck] = make_float2(o[nt][2], o[nt][3]);
    }
}

// ------------------------- merge partials -> out[:, 512:576] ----------------
__global__ __launch_bounds__(256) void merge_kernel(float* __restrict__ out) {
    const int d = threadIdx.x;
    const int qg = blockIdx.x * 4 + threadIdx.y;
    const int b = qg / TT;
    const int t = qg % TT;
    const int qt = t / BM;
    const int qloc = t % BM;
    const int nc = t / CHUNK + 1;
    const size_t base = (size_t)(b * QT + qt) * NCH;

    float M = -1e30f;
#pragma unroll 1
    for (int cc = 0; cc < nc; cc++)
        M = fmaxf(M, g_pm[(base + cc) * BM + qloc]);

    float L = 0.f, acc = 0.f;
#pragma unroll 1
    for (int cc = 0; cc < nc; cc++) {
        float w = ex2f(g_pm[(base + cc) * BM + qloc] - M);
        L += w * g_pl[(base + cc) * BM + qloc];
        acc += w * g_po[((base + cc) * BM + qloc) * KD + d];
    }
    out[(size_t)qg * OUTC + CC + d] = acc / L;
}

// ------------------------- launch -------------------------------------------
extern "C" void kernel_launch(void* const* d_in, const int* in_sizes, int n_in,
                              void* d_out, int out_size) {
    (void)in_sizes; (void)n_in; (void)out_size;
    const float* x  = (const float*)d_in[0];
    const float* Wq = (const float*)d_in[1];
    const float* bq = (const float*)d_in[2];
    const float* Wk = (const float*)d_in[3];
    const float* bk = (const float*)d_in[4];
    const float* Wv = (const float*)d_in[5];
    const float* bv = (const float*)d_in[6];
    float* out = (float*)d_out;

    const int M = NB * TT;  // 16384 rows

    cudaFuncSetAttribute(flash_partial,
                         cudaFuncAttributeMaxDynamicSharedMemorySize,
                         FLASH_SMEM_BYTES);

    qkv_kernel<<<dim3(M / 64, 3), 256>>>(x, Wq, bq, Wk, bk, Wv, bv);
    xcopy_kernel<<<M, 128>>>((const float4*)x, (float4*)out);
    flash_partial<<<dim3(NCH, QT, NB), 256, FLASH_SMEM_BYTES>>>();
    merge_kernel<<<M / 4, dim3(64, 4)>>>(out);
}

// round 8
// speedup vs baseline: 9.3595x; 1.6642x over previous
#include <cuda_runtime.h>
#include <cstdint>

// Problem constants
#define NB 4
#define TT 4096
#define CC 512
#define KD 64
#define BM2 128          // queries per flash block
#define CHUNK 512        // keys per flash unit (split-K)
#define QT2 (TT/BM2)     // 32
#define NCH (TT/CHUNK)   // 8
#define OUTC 576

// (1/sqrt(64)) * log2(e): softmax in exp2 domain
#define QS 0.1803368801111244f

#define SQ 68
#define SV 72
#define FLASH_SMEM_BYTES ((128*SQ + 64*SQ + 64*SV) * 4)
#define QKV_SMEM_BYTES   ((128*SQ + 64*SQ) * 4)

// ------------------------- scratch ------------------------------------------
__device__ float g_q[NB * TT * KD];
__device__ float g_k[NB * TT * KD];
__device__ float g_v[NB * TT * KD];
__device__ float g_po[(size_t)NB * QT2 * NCH * BM2 * KD];
__device__ float g_pm[NB * QT2 * NCH * BM2];
__device__ float g_pl[NB * QT2 * NCH * BM2];

// ------------------------- helpers -----------------------------------------
__device__ __forceinline__ float ex2f(float x) {
    float r;
    asm("ex2.approx.f32 %0, %1;" : "=f"(r) : "f"(x));
    return r;
}
__device__ __forceinline__ void mma_tf32(float& d0, float& d1, float& d2, float& d3,
                                         unsigned a0, unsigned a1, unsigned a2, unsigned a3,
                                         unsigned b0, unsigned b1) {
    asm volatile(
        "mma.sync.aligned.m16n8k8.row.col.f32.tf32.tf32.f32 "
        "{%0,%1,%2,%3}, {%4,%5,%6,%7}, {%8,%9}, {%0,%1,%2,%3};"
        : "+f"(d0), "+f"(d1), "+f"(d2), "+f"(d3)
        : "r"(a0), "r"(a1), "r"(a2), "r"(a3), "r"(b0), "r"(b1));
}
#define F2U __float_as_uint

// ------------------------- QKV projection (tf32 mma) ------------------------
// grid (128, 3); block 128 = 4 warps; tile 128 rows x 64 cols; K in steps of 64.
__global__ __launch_bounds__(128) void qkv_kernel(
    const float* __restrict__ x,
    const float* __restrict__ Wq, const float* __restrict__ bq,
    const float* __restrict__ Wk, const float* __restrict__ bk,
    const float* __restrict__ Wv, const float* __restrict__ bv) {
    extern __shared__ float sm[];
    float* xs = sm;              // [128][SQ]
    float* ws = xs + 128 * SQ;   // [64 n][SQ]  (W transposed: ws[n][k])

    const int which = blockIdx.y;
    const float* W = (which == 0) ? Wq : (which == 1) ? Wk : Wv;
    const float* bias = (which == 0) ? bq : (which == 1) ? bk : bv;
    float* outp = (which == 0) ? g_q : (which == 1) ? g_k : g_v;
    const float scale = (which == 0) ? QS : 1.0f;

    const int row0 = blockIdx.x * 128;
    const int tid = threadIdx.x;
    const int lane = tid & 31;
    const int warp = tid >> 5;
    const int wr0 = warp * 32;
    const int gid = lane >> 2;
    const int tig = lane & 3;

    float o[2][8][4];
#pragma unroll
    for (int t = 0; t < 2; t++)
#pragma unroll
        for (int nt = 0; nt < 8; nt++)
#pragma unroll
            for (int r = 0; r < 4; r++) o[t][nt][r] = 0.f;

    const int wkk = tid & 63;         // k index for W staging
    const int whalf = tid >> 6;       // 0/1

    for (int ks0 = 0; ks0 < CC; ks0 += 64) {
        __syncthreads();
        // stage x tile [128 rows][64 k]
#pragma unroll
        for (int i = 0; i < 16; i++) {
            int f = tid + i * 128;
            int row = f >> 4, c4 = (f & 15) * 4;
            float4 v = ((const float4*)x)[(size_t)(row0 + row) * (CC / 4) + (ks0 >> 2) + (f & 15)];
            *(float4*)&xs[row * SQ + c4] = v;
        }
        // stage W transposed: ws[n][k] = W[ks0+k][n]
#pragma unroll
        for (int i = 0; i < 8; i++) {
            int n4 = whalf + i * 2;   // 0..15
            float4 wv = ((const float4*)W)[(size_t)(ks0 + wkk) * (KD / 4) + n4];
            ws[(n4 * 4 + 0) * SQ + wkk] = wv.x;
            ws[(n4 * 4 + 1) * SQ + wkk] = wv.y;
            ws[(n4 * 4 + 2) * SQ + wkk] = wv.z;
            ws[(n4 * 4 + 3) * SQ + wkk] = wv.w;
        }
        __syncthreads();

#pragma unroll
        for (int k8 = 0; k8 < 8; k8++) {
            const int ca = k8 * 8 + tig;
            unsigned bf[8][2];
#pragma unroll
            for (int nt = 0; nt < 8; nt++) {
                bf[nt][0] = F2U(ws[(nt * 8 + gid) * SQ + ca]);
                bf[nt][1] = F2U(ws[(nt * 8 + gid) * SQ + ca + 4]);
            }
#pragma unroll
            for (int t = 0; t < 2; t++) {
                int rb = wr0 + t * 16;
                unsigned a0 = F2U(xs[(rb + gid) * SQ + ca]);
                unsigned a1 = F2U(xs[(rb + gid + 8) * SQ + ca]);
                unsigned a2 = F2U(xs[(rb + gid) * SQ + ca + 4]);
                unsigned a3 = F2U(xs[(rb + gid + 8) * SQ + ca + 4]);
#pragma unroll
                for (int nt = 0; nt < 8; nt++)
                    mma_tf32(o[t][nt][0], o[t][nt][1], o[t][nt][2], o[t][nt][3],
                             a0, a1, a2, a3, bf[nt][0], bf[nt][1]);
            }
        }
    }

    // epilogue: bias + scale
#pragma unroll
    for (int t = 0; t < 2; t++) {
#pragma unroll
        for (int nt = 0; nt < 8; nt++) {
            int col = nt * 8 + 2 * tig;
            float b0 = bias[col], b1 = bias[col + 1];
            int rowA = row0 + wr0 + t * 16 + gid;
            float2 ra, rb;
            ra.x = (o[t][nt][0] + b0) * scale;
            ra.y = (o[t][nt][1] + b1) * scale;
            rb.x = (o[t][nt][2] + b0) * scale;
            rb.y = (o[t][nt][3] + b1) * scale;
            *(float2*)&outp[(size_t)rowA * KD + col] = ra;
            *(float2*)&outp[(size_t)(rowA + 8) * KD + col] = rb;
        }
    }
}

// ------------------------- x -> out[:, :512] copy ---------------------------
__global__ __launch_bounds__(128) void xcopy_kernel(const float4* __restrict__ x4,
                                                    float4* __restrict__ out4) {
    size_t row = blockIdx.x;
    int c = threadIdx.x;
    out4[row * (OUTC / 4) + c] = x4[row * (CC / 4) + c];
}

// ------------------------- flash partial (tf32 mma, warp-rows) --------------
// grid (NCH, QT2, NB); 128 threads = 4 warps; warp owns 32 query rows.
__global__ __launch_bounds__(128) void flash_partial() {
    extern __shared__ float sm[];
    float* qs = sm;               // [128][SQ]
    float* ks = qs + 128 * SQ;    // [64][SQ]
    float* vs = ks + 64 * SQ;     // [64][SV]

    const int c = blockIdx.x;
    const int qt = blockIdx.y;
    const int b = blockIdx.z;
    const int qend = (qt + 1) * BM2;
    const int k0 = c * CHUNK;
    if (k0 >= qend) return;
    const int kend = (k0 + CHUNK < qend) ? (k0 + CHUNK) : qend;

    const int tid = threadIdx.x;
    const int lane = tid & 31;
    const int warp = tid >> 5;
    const int wr0 = warp * 32;
    const int gid = lane >> 2;
    const int tig = lane & 3;
    const int wq0 = qt * BM2 + wr0;      // global first row of this warp

    // stage Q tile (once)
    {
        const float4* qp = (const float4*)(g_q + ((size_t)b * TT + qt * BM2) * KD);
#pragma unroll
        for (int i = 0; i < 16; i++) {
            int f = tid + i * 128;
            int row = f >> 4, c4 = (f & 15) * 4;
            *(float4*)&qs[row * SQ + c4] = qp[f];
        }
    }

    float o[2][8][4];
    float m[2][2], l[2][2];
#pragma unroll
    for (int t = 0; t < 2; t++) {
#pragma unroll
        for (int nt = 0; nt < 8; nt++)
#pragma unroll
            for (int r = 0; r < 4; r++) o[t][nt][r] = 0.f;
        m[t][0] = -1e30f; m[t][1] = -1e30f;
        l[t][0] = 0.f; l[t][1] = 0.f;
    }

    const unsigned fullm = 0xffffffffu;
    const int srcA = (lane & ~3) | (tig >> 1);
    const int srcB = srcA + 2;
    const bool sel = (tig & 1);

    for (int s0 = k0; s0 < kend; s0 += 64) {
        __syncthreads();
        {
            const float4* kp = (const float4*)(g_k + ((size_t)b * TT + s0) * KD);
            const float4* vp = (const float4*)(g_v + ((size_t)b * TT + s0) * KD);
#pragma unroll
            for (int i = 0; i < 8; i++) {
                int f = tid + i * 128;
                int row = f >> 4, c4 = (f & 15) * 4;
                *(float4*)&ks[row * SQ + c4] = kp[f];
                *(float4*)&vs[row * SV + c4] = vp[f];
            }
        }
        __syncthreads();

        if (s0 > wq0 + 31) continue;     // entire subtile above this warp's rows

        // ---- S = Q K^T ----
        float sacc[2][8][4];
#pragma unroll
        for (int t = 0; t < 2; t++)
#pragma unroll
            for (int nt = 0; nt < 8; nt++)
#pragma unroll
                for (int r = 0; r < 4; r++) sacc[t][nt][r] = 0.f;

#pragma unroll
        for (int k8 = 0; k8 < 8; k8++) {
            const int ca = k8 * 8 + tig;
            unsigned bf[8][2];
#pragma unroll
            for (int nt = 0; nt < 8; nt++) {
                bf[nt][0] = F2U(ks[(nt * 8 + gid) * SQ + ca]);
                bf[nt][1] = F2U(ks[(nt * 8 + gid) * SQ + ca + 4]);
            }
#pragma unroll
            for (int t = 0; t < 2; t++) {
                int rb = wr0 + t * 16;
                unsigned a0 = F2U(qs[(rb + gid) * SQ + ca]);
                unsigned a1 = F2U(qs[(rb + gid + 8) * SQ + ca]);
                unsigned a2 = F2U(qs[(rb + gid) * SQ + ca + 4]);
                unsigned a3 = F2U(qs[(rb + gid + 8) * SQ + ca + 4]);
#pragma unroll
                for (int nt = 0; nt < 8; nt++)
                    mma_tf32(sacc[t][nt][0], sacc[t][nt][1], sacc[t][nt][2], sacc[t][nt][3],
                             a0, a1, a2, a3, bf[nt][0], bf[nt][1]);
            }
        }

        // ---- causal mask ----
        if (s0 + 63 > wq0) {
#pragma unroll
            for (int t = 0; t < 2; t++) {
                int rq0 = wq0 + t * 16 + gid;
                int rq1 = rq0 + 8;
#pragma unroll
                for (int nt = 0; nt < 8; nt++) {
                    int ck = s0 + nt * 8 + 2 * tig;
                    if (ck > rq0) sacc[t][nt][0] = -1e30f;
                    if (ck + 1 > rq0) sacc[t][nt][1] = -1e30f;
                    if (ck > rq1) sacc[t][nt][2] = -1e30f;
                    if (ck + 1 > rq1) sacc[t][nt][3] = -1e30f;
                }
            }
        }

        // ---- warp-local online softmax ----
#pragma unroll
        for (int t = 0; t < 2; t++) {
            float mx0 = -1e30f, mx1 = -1e30f;
#pragma unroll
            for (int nt = 0; nt < 8; nt++) {
                mx0 = fmaxf(mx0, fmaxf(sacc[t][nt][0], sacc[t][nt][1]));
                mx1 = fmaxf(mx1, fmaxf(sacc[t][nt][2], sacc[t][nt][3]));
            }
            mx0 = fmaxf(mx0, __shfl_xor_sync(fullm, mx0, 1));
            mx0 = fmaxf(mx0, __shfl_xor_sync(fullm, mx0, 2));
            mx1 = fmaxf(mx1, __shfl_xor_sync(fullm, mx1, 1));
            mx1 = fmaxf(mx1, __shfl_xor_sync(fullm, mx1, 2));
            float mn0 = fmaxf(m[t][0], mx0);
            float mn1 = fmaxf(m[t][1], mx1);
            float corr0 = ex2f(m[t][0] - mn0);
            float corr1 = ex2f(m[t][1] - mn1);
            m[t][0] = mn0; m[t][1] = mn1;
            float sum0 = 0.f, sum1 = 0.f;
#pragma unroll
            for (int nt = 0; nt < 8; nt++) {
                sacc[t][nt][0] = ex2f(sacc[t][nt][0] - mn0);
                sacc[t][nt][1] = ex2f(sacc[t][nt][1] - mn0);
                sacc[t][nt][2] = ex2f(sacc[t][nt][2] - mn1);
                sacc[t][nt][3] = ex2f(sacc[t][nt][3] - mn1);
                sum0 += sacc[t][nt][0] + sacc[t][nt][1];
                sum1 += sacc[t][nt][2] + sacc[t][nt][3];
            }
            sum0 += __shfl_xor_sync(fullm, sum0, 1);
            sum0 += __shfl_xor_sync(fullm, sum0, 2);
            sum1 += __shfl_xor_sync(fullm, sum1, 1);
            sum1 += __shfl_xor_sync(fullm, sum1, 2);
            l[t][0] = l[t][0] * corr0 + sum0;
            l[t][1] = l[t][1] * corr1 + sum1;
#pragma unroll
            for (int nt = 0; nt < 8; nt++) {
                o[t][nt][0] *= corr0; o[t][nt][1] *= corr0;
                o[t][nt][2] *= corr1; o[t][nt][3] *= corr1;
            }
        }

        // ---- O += P V : C-frag -> A-frag via quad shfl ----
#pragma unroll
        for (int k8 = 0; k8 < 8; k8++) {
            unsigned a[2][4];
#pragma unroll
            for (int t = 0; t < 2; t++) {
                float v0 = __shfl_sync(fullm, sacc[t][k8][0], srcA);
                float v1 = __shfl_sync(fullm, sacc[t][k8][1], srcA);
                a[t][0] = F2U(sel ? v1 : v0);
                float w0 = __shfl_sync(fullm, sacc[t][k8][0], srcB);
                float w1 = __shfl_sync(fullm, sacc[t][k8][1], srcB);
                a[t][2] = F2U(sel ? w1 : w0);
                float u0 = __shfl_sync(fullm, sacc[t][k8][2], srcA);
                float u1 = __shfl_sync(fullm, sacc[t][k8][3], srcA);
                a[t][1] = F2U(sel ? u1 : u0);
                float x0 = __shfl_sync(fullm, sacc[t][k8][2], srcB);
                float x1 = __shfl_sync(fullm, sacc[t][k8][3], srcB);
                a[t][3] = F2U(sel ? x1 : x0);
            }
#pragma unroll
            for (int nt = 0; nt < 8; nt++) {
                int vc = nt * 8 + gid;
                unsigned b0 = F2U(vs[(k8 * 8 + tig) * SV + vc]);
                unsigned b1 = F2U(vs[(k8 * 8 + tig + 4) * SV + vc]);
                mma_tf32(o[0][nt][0], o[0][nt][1], o[0][nt][2], o[0][nt][3],
                         a[0][0], a[0][1], a[0][2], a[0][3], b0, b1);
                mma_tf32(o[1][nt][0], o[1][nt][1], o[1][nt][2], o[1][nt][3],
                         a[1][0], a[1][1], a[1][2], a[1][3], b0, b1);
            }
        }
    }

    // ---- write partials ----
    const size_t unit = ((size_t)(b * QT2 + qt) * NCH + c);
    if (tig == 0) {
#pragma unroll
        for (int t = 0; t < 2; t++) {
            g_pm[unit * BM2 + wr0 + t * 16 + gid] = m[t][0];
            g_pm[unit * BM2 + wr0 + t * 16 + gid + 8] = m[t][1];
            g_pl[unit * BM2 + wr0 + t * 16 + gid] = l[t][0];
            g_pl[unit * BM2 + wr0 + t * 16 + gid + 8] = l[t][1];
        }
    }
    float* po = g_po + unit * BM2 * KD;
#pragma unroll
    for (int t = 0; t < 2; t++) {
        int rA = wr0 + t * 16 + gid;
#pragma unroll
        for (int nt = 0; nt < 8; nt++) {
            int col = nt * 8 + 2 * tig;
            *(float2*)&po[(size_t)rA * KD + col] = make_float2(o[t][nt][0], o[t][nt][1]);
            *(float2*)&po[(size_t)(rA + 8) * KD + col] = make_float2(o[t][nt][2], o[t][nt][3]);
        }
    }
}

// ------------------------- merge partials -> out[:, 512:576] ----------------
// block (16,16): tx -> 4 dims (float4), ty -> query.
__global__ __launch_bounds__(256) void merge_kernel(float* __restrict__ out) {
    const int tx = threadIdx.x;
    const int q = blockIdx.x * 16 + threadIdx.y;
    const int b = q / TT;
    const int t = q % TT;
    const int qt = t / BM2;
    const int qloc = t % BM2;
    const int nc = t / CHUNK + 1;
    const size_t base = (size_t)(b * QT2 + qt) * NCH;

    float M = -1e30f;
#pragma unroll 1
    for (int c = 0; c < nc; c++)
        M = fmaxf(M, g_pm[(base + c) * BM2 + qloc]);

    float L = 0.f;
    float4 acc = make_float4(0.f, 0.f, 0.f, 0.f);
#pragma unroll 1
    for (int c = 0; c < nc; c++) {
        float w = ex2f(g_pm[(base + c) * BM2 + qloc] - M);
        L += w * g_pl[(base + c) * BM2 + qloc];
        float4 p = *(const float4*)&g_po[((base + c) * BM2 + qloc) * KD + tx * 4];
        acc.x += w * p.x; acc.y += w * p.y;
        acc.z += w * p.z; acc.w += w * p.w;
    }
    float inv = 1.0f / L;
    float4 r = make_float4(acc.x * inv, acc.y * inv, acc.z * inv, acc.w * inv);
    *(float4*)&out[(size_t)q * OUTC + CC + tx * 4] = r;
}

// ------------------------- launch -------------------------------------------
extern "C" void kernel_launch(void* const* d_in, const int* in_sizes, int n_in,
                              void* d_out, int out_size) {
    (void)in_sizes; (void)n_in; (void)out_size;
    const float* x  = (const float*)d_in[0];
    const float* Wq = (const float*)d_in[1];
    const float* bq = (const float*)d_in[2];
    const float* Wk = (const float*)d_in[3];
    const float* bk = (const float*)d_in[4];
    const float* Wv = (const float*)d_in[5];
    const float* bv = (const float*)d_in[6];
    float* out = (float*)d_out;

    const int M = NB * TT;  // 16384

    cudaFuncSetAttribute(flash_partial,
                         cudaFuncAttributeMaxDynamicSharedMemorySize,
                         FLASH_SMEM_BYTES);
    cudaFuncSetAttribute(qkv_kernel,
                         cudaFuncAttributeMaxDynamicSharedMemorySize,
                         QKV_SMEM_BYTES);

    qkv_kernel<<<dim3(M / 128, 3), 128, QKV_SMEM_BYTES>>>(x, Wq, bq, Wk, bk, Wv, bv);
    xcopy_kernel<<<M, 128>>>((const float4*)x, (float4*)out);
    flash_partial<<<dim3(NCH, QT2, NB), 128, FLASH_SMEM_BYTES>>>();
    merge_kernel<<<M / 16, dim3(16, 16)>>>(out);
}

// round 10
// speedup vs baseline: 13.1392x; 1.4038x over previous
#include <cuda_runtime.h>
#include <cuda_bf16.h>
#include <cstdint>

// Problem constants
#define NB 4
#define TT 4096
#define CC 512
#define KD 64
#define BM2 128          // queries per flash block
#define CHUNK 512        // keys per flash unit (split-K)
#define QT2 (TT/BM2)     // 32
#define NCH (TT/CHUNK)   // 8
#define OUTC 576

// (1/sqrt(64)) * log2(e): softmax in exp2 domain
#define QS 0.1803368801111244f

#define SQ 68            // fp32 stride (qkv staging)
#define SB 72            // bf16 stride (flash tiles)
#define QKV_SMEM_BYTES   ((128*SQ + 64*SQ) * 4)

// ------------------------- scratch ------------------------------------------
__device__ __align__(16) __nv_bfloat16 g_qb[NB * TT * KD];   // [t][d], q pre-scaled
__device__ __align__(16) __nv_bfloat16 g_kb[NB * TT * KD];   // [t][d]
__device__ __align__(16) __nv_bfloat16 g_vt[NB * KD * TT];   // [d][t] transposed
__device__ float g_po[(size_t)NB * QT2 * NCH * BM2 * KD];
__device__ float g_pm[NB * QT2 * NCH * BM2];
__device__ float g_pl[NB * QT2 * NCH * BM2];

// ------------------------- helpers -----------------------------------------
__device__ __forceinline__ float ex2f(float x) {
    float r;
    asm("ex2.approx.f32 %0, %1;" : "=f"(r) : "f"(x));
    return r;
}
__device__ __forceinline__ unsigned cvt_bf2(float hi, float lo) {
    unsigned d;
    asm("cvt.rn.bf16x2.f32 %0, %1, %2;" : "=r"(d) : "f"(hi), "f"(lo));
    return d;
}
__device__ __forceinline__ void mma_tf32(float& d0, float& d1, float& d2, float& d3,
                                         unsigned a0, unsigned a1, unsigned a2, unsigned a3,
                                         unsigned b0, unsigned b1) {
    asm volatile(
        "mma.sync.aligned.m16n8k8.row.col.f32.tf32.tf32.f32 "
        "{%0,%1,%2,%3}, {%4,%5,%6,%7}, {%8,%9}, {%0,%1,%2,%3};"
        : "+f"(d0), "+f"(d1), "+f"(d2), "+f"(d3)
        : "r"(a0), "r"(a1), "r"(a2), "r"(a3), "r"(b0), "r"(b1));
}
__device__ __forceinline__ void mma_bf16(float& d0, float& d1, float& d2, float& d3,
                                         unsigned a0, unsigned a1, unsigned a2, unsigned a3,
                                         unsigned b0, unsigned b1) {
    asm volatile(
        "mma.sync.aligned.m16n8k16.row.col.f32.bf16.bf16.f32 "
        "{%0,%1,%2,%3}, {%4,%5,%6,%7}, {%8,%9}, {%0,%1,%2,%3};"
        : "+f"(d0), "+f"(d1), "+f"(d2), "+f"(d3)
        : "r"(a0), "r"(a1), "r"(a2), "r"(a3), "r"(b0), "r"(b1));
}
#define F2U __float_as_uint

// ------------------------- QKV projection (tf32 mma, bf16 out) --------------
// grid (128, 3); block 128 = 4 warps; tile 128 rows x 64 cols; K steps of 64.
__global__ __launch_bounds__(128) void qkv_kernel(
    const float* __restrict__ x,
    const float* __restrict__ Wq, const float* __restrict__ bq,
    const float* __restrict__ Wk, const float* __restrict__ bk,
    const float* __restrict__ Wv, const float* __restrict__ bv) {
    extern __shared__ float sm[];
    float* xs = sm;              // [128][SQ]
    float* ws = xs + 128 * SQ;   // [64 n][SQ]  (W transposed: ws[n][k])

    const int which = blockIdx.y;
    const float* W = (which == 0) ? Wq : (which == 1) ? Wk : Wv;
    const float* bias = (which == 0) ? bq : (which == 1) ? bk : bv;
    const float scale = (which == 0) ? QS : 1.0f;

    const int row0 = blockIdx.x * 128;
    const int tid = threadIdx.x;
    const int lane = tid & 31;
    const int warp = tid >> 5;
    const int wr0 = warp * 32;
    const int gid = lane >> 2;
    const int tig = lane & 3;

    float o[2][8][4];
#pragma unroll
    for (int t = 0; t < 2; t++)
#pragma unroll
        for (int nt = 0; nt < 8; nt++)
#pragma unroll
            for (int r = 0; r < 4; r++) o[t][nt][r] = 0.f;

    const int wkk = tid & 63;
    const int whalf = tid >> 6;

    for (int ks0 = 0; ks0 < CC; ks0 += 64) {
        __syncthreads();
#pragma unroll
        for (int i = 0; i < 16; i++) {
            int f = tid + i * 128;
            int row = f >> 4, c4 = (f & 15) * 4;
            float4 v = ((const float4*)x)[(size_t)(row0 + row) * (CC / 4) + (ks0 >> 2) + (f & 15)];
            *(float4*)&xs[row * SQ + c4] = v;
        }
#pragma unroll
        for (int i = 0; i < 8; i++) {
            int n4 = whalf + i * 2;
            float4 wv = ((const float4*)W)[(size_t)(ks0 + wkk) * (KD / 4) + n4];
            ws[(n4 * 4 + 0) * SQ + wkk] = wv.x;
            ws[(n4 * 4 + 1) * SQ + wkk] = wv.y;
            ws[(n4 * 4 + 2) * SQ + wkk] = wv.z;
            ws[(n4 * 4 + 3) * SQ + wkk] = wv.w;
        }
        __syncthreads();

#pragma unroll
        for (int k8 = 0; k8 < 8; k8++) {
            const int ca = k8 * 8 + tig;
            unsigned bf[8][2];
#pragma unroll
            for (int nt = 0; nt < 8; nt++) {
                bf[nt][0] = F2U(ws[(nt * 8 + gid) * SQ + ca]);
                bf[nt][1] = F2U(ws[(nt * 8 + gid) * SQ + ca + 4]);
            }
#pragma unroll
            for (int t = 0; t < 2; t++) {
                int rb = wr0 + t * 16;
                unsigned a0 = F2U(xs[(rb + gid) * SQ + ca]);
                unsigned a1 = F2U(xs[(rb + gid + 8) * SQ + ca]);
                unsigned a2 = F2U(xs[(rb + gid) * SQ + ca + 4]);
                unsigned a3 = F2U(xs[(rb + gid + 8) * SQ + ca + 4]);
#pragma unroll
                for (int nt = 0; nt < 8; nt++)
                    mma_tf32(o[t][nt][0], o[t][nt][1], o[t][nt][2], o[t][nt][3],
                             a0, a1, a2, a3, bf[nt][0], bf[nt][1]);
            }
        }
    }

    // epilogue: bias + scale -> bf16 (q/k: [t][d]; v: transposed [d][t])
#pragma unroll
    for (int t = 0; t < 2; t++) {
#pragma unroll
        for (int nt = 0; nt < 8; nt++) {
            int col = nt * 8 + 2 * tig;
            float b0 = bias[col], b1 = bias[col + 1];
            int rowA = row0 + wr0 + t * 16 + gid;
            float va0 = (o[t][nt][0] + b0) * scale;
            float va1 = (o[t][nt][1] + b1) * scale;
            float vb0 = (o[t][nt][2] + b0) * scale;
            float vb1 = (o[t][nt][3] + b1) * scale;
            if (which == 2) {
                int bb = rowA >> 12;
                int tA = rowA & 4095;
                g_vt[((size_t)(bb * KD + col)) * TT + tA]     = __float2bfloat16_rn(va0);
                g_vt[((size_t)(bb * KD + col + 1)) * TT + tA] = __float2bfloat16_rn(va1);
                g_vt[((size_t)(bb * KD + col)) * TT + tA + 8]     = __float2bfloat16_rn(vb0);
                g_vt[((size_t)(bb * KD + col + 1)) * TT + tA + 8] = __float2bfloat16_rn(vb1);
            } else {
                __nv_bfloat16* dst = (which == 0) ? g_qb : g_kb;
                *(unsigned*)&dst[(size_t)rowA * KD + col] = cvt_bf2(va1, va0);
                *(unsigned*)&dst[(size_t)(rowA + 8) * KD + col] = cvt_bf2(vb1, vb0);
            }
        }
    }
}

// ------------------------- flash partial (bf16 mma, warp-rows) --------------
// grid (NCH, QT2, NB); 128 threads = 4 warps; warp owns 32 query rows.
__global__ __launch_bounds__(128) void flash_partial() {
    __shared__ __align__(16) __nv_bfloat16 qs[128 * SB];
    __shared__ __align__(16) __nv_bfloat16 ks[64 * SB];
    __shared__ __align__(16) __nv_bfloat16 vt[64 * SB];   // [vdim][key]

    const int c = blockIdx.x;
    const int qt = blockIdx.y;
    const int b = blockIdx.z;
    const int qend = (qt + 1) * BM2;
    const int k0 = c * CHUNK;
    if (k0 >= qend) return;
    const int kend = (k0 + CHUNK < qend) ? (k0 + CHUNK) : qend;

    const int tid = threadIdx.x;
    const int lane = tid & 31;
    const int warp = tid >> 5;
    const int wr0 = warp * 32;
    const int gid = lane >> 2;
    const int tig = lane & 3;
    const int wq0 = qt * BM2 + wr0;
    const unsigned fullm = 0xffffffffu;

    // stage Q tile (once): 128 rows x 64 bf16 = 1024 x 16B chunks
    {
        const uint4* qp = (const uint4*)(g_qb + ((size_t)b * TT + qt * BM2) * KD);
#pragma unroll
        for (int i = 0; i < 8; i++) {
            int f = tid + i * 128;
            int row = f >> 3, ch = f & 7;
            *(uint4*)&qs[row * SB + ch * 8] = qp[f];
        }
    }

    float o[2][8][4];
    float m[2][2], l[2][2];
#pragma unroll
    for (int t = 0; t < 2; t++) {
#pragma unroll
        for (int nt = 0; nt < 8; nt++)
#pragma unroll
            for (int r = 0; r < 4; r++) o[t][nt][r] = 0.f;
        m[t][0] = -1e30f; m[t][1] = -1e30f;
        l[t][0] = 0.f; l[t][1] = 0.f;
    }

    for (int s0 = k0; s0 < kend; s0 += 64) {
        __syncthreads();
        {
            const uint4* kp = (const uint4*)(g_kb + ((size_t)b * TT + s0) * KD);
#pragma unroll
            for (int i = 0; i < 4; i++) {
                int f = tid + i * 128;
                int row = f >> 3, ch = f & 7;
                *(uint4*)&ks[row * SB + ch * 8] = kp[f];
                // V^T: row d, 64 keys starting at s0
                *(uint4*)&vt[row * SB + ch * 8] =
                    ((const uint4*)(g_vt + ((size_t)(b * KD + row)) * TT + s0))[ch];
            }
        }
        __syncthreads();

        if (s0 > wq0 + 31) continue;

        // ---- S = Q K^T (bf16 m16n8k16) ----
        float sacc[2][8][4];
#pragma unroll
        for (int t = 0; t < 2; t++)
#pragma unroll
            for (int nt = 0; nt < 8; nt++)
#pragma unroll
                for (int r = 0; r < 4; r++) sacc[t][nt][r] = 0.f;

#pragma unroll
        for (int kk = 0; kk < 4; kk++) {
            const int ca = kk * 16 + 2 * tig;
            unsigned bf[8][2];
#pragma unroll
            for (int nt = 0; nt < 8; nt++) {
                bf[nt][0] = *(const unsigned*)&ks[(nt * 8 + gid) * SB + ca];
                bf[nt][1] = *(const unsigned*)&ks[(nt * 8 + gid) * SB + ca + 8];
            }
#pragma unroll
            for (int t = 0; t < 2; t++) {
                int rb = wr0 + t * 16;
                unsigned a0 = *(const unsigned*)&qs[(rb + gid) * SB + ca];
                unsigned a1 = *(const unsigned*)&qs[(rb + gid + 8) * SB + ca];
                unsigned a2 = *(const unsigned*)&qs[(rb + gid) * SB + ca + 8];
                unsigned a3 = *(const unsigned*)&qs[(rb + gid + 8) * SB + ca + 8];
#pragma unroll
                for (int nt = 0; nt < 8; nt++)
                    mma_bf16(sacc[t][nt][0], sacc[t][nt][1], sacc[t][nt][2], sacc[t][nt][3],
                             a0, a1, a2, a3, bf[nt][0], bf[nt][1]);
            }
        }

        // ---- causal mask ----
        if (s0 + 63 > wq0) {
#pragma unroll
            for (int t = 0; t < 2; t++) {
                int rq0 = wq0 + t * 16 + gid;
                int rq1 = rq0 + 8;
#pragma unroll
                for (int nt = 0; nt < 8; nt++) {
                    int ck = s0 + nt * 8 + 2 * tig;
                    if (ck > rq0) sacc[t][nt][0] = -1e30f;
                    if (ck + 1 > rq0) sacc[t][nt][1] = -1e30f;
                    if (ck > rq1) sacc[t][nt][2] = -1e30f;
                    if (ck + 1 > rq1) sacc[t][nt][3] = -1e30f;
                }
            }
        }

        // ---- warp-local online softmax ----
#pragma unroll
        for (int t = 0; t < 2; t++) {
            float mx0 = -1e30f, mx1 = -1e30f;
#pragma unroll
            for (int nt = 0; nt < 8; nt++) {
                mx0 = fmaxf(mx0, fmaxf(sacc[t][nt][0], sacc[t][nt][1]));
                mx1 = fmaxf(mx1, fmaxf(sacc[t][nt][2], sacc[t][nt][3]));
            }
            mx0 = fmaxf(mx0, __shfl_xor_sync(fullm, mx0, 1));
            mx0 = fmaxf(mx0, __shfl_xor_sync(fullm, mx0, 2));
            mx1 = fmaxf(mx1, __shfl_xor_sync(fullm, mx1, 1));
            mx1 = fmaxf(mx1, __shfl_xor_sync(fullm, mx1, 2));
            float mn0 = fmaxf(m[t][0], mx0);
            float mn1 = fmaxf(m[t][1], mx1);
            float corr0 = ex2f(m[t][0] - mn0);
            float corr1 = ex2f(m[t][1] - mn1);
            m[t][0] = mn0; m[t][1] = mn1;
            float sum0 = 0.f, sum1 = 0.f;
#pragma unroll
            for (int nt = 0; nt < 8; nt++) {
                sacc[t][nt][0] = ex2f(sacc[t][nt][0] - mn0);
                sacc[t][nt][1] = ex2f(sacc[t][nt][1] - mn0);
                sacc[t][nt][2] = ex2f(sacc[t][nt][2] - mn1);
                sacc[t][nt][3] = ex2f(sacc[t][nt][3] - mn1);
                sum0 += sacc[t][nt][0] + sacc[t][nt][1];
                sum1 += sacc[t][nt][2] + sacc[t][nt][3];
            }
            sum0 += __shfl_xor_sync(fullm, sum0, 1);
            sum0 += __shfl_xor_sync(fullm, sum0, 2);
            sum1 += __shfl_xor_sync(fullm, sum1, 1);
            sum1 += __shfl_xor_sync(fullm, sum1, 2);
            l[t][0] = l[t][0] * corr0 + sum0;
            l[t][1] = l[t][1] * corr1 + sum1;
#pragma unroll
            for (int nt = 0; nt < 8; nt++) {
                o[t][nt][0] *= corr0; o[t][nt][1] *= corr0;
                o[t][nt][2] *= corr1; o[t][nt][3] *= corr1;
            }
        }

        // ---- O += P V: C-frag == A-frag layout for k16 -> just cvt ----
#pragma unroll
        for (int kk = 0; kk < 4; kk++) {
            unsigned a[2][4];
#pragma unroll
            for (int t = 0; t < 2; t++) {
                a[t][0] = cvt_bf2(sacc[t][2 * kk][1], sacc[t][2 * kk][0]);
                a[t][1] = cvt_bf2(sacc[t][2 * kk][3], sacc[t][2 * kk][2]);
                a[t][2] = cvt_bf2(sacc[t][2 * kk + 1][1], sacc[t][2 * kk + 1][0]);
                a[t][3] = cvt_bf2(sacc[t][2 * kk + 1][3], sacc[t][2 * kk + 1][2]);
            }
            const int kb = kk * 16 + 2 * tig;
#pragma unroll
            for (int nt = 0; nt < 8; nt++) {
                int vc = nt * 8 + gid;
                unsigned b0 = *(const unsigned*)&vt[vc * SB + kb];
                unsigned b1 = *(const unsigned*)&vt[vc * SB + kb + 8];
                mma_bf16(o[0][nt][0], o[0][nt][1], o[0][nt][2], o[0][nt][3],
                         a[0][0], a[0][1], a[0][2], a[0][3], b0, b1);
                mma_bf16(o[1][nt][0], o[1][nt][1], o[1][nt][2], o[1][nt][3],
                         a[1][0], a[1][1], a[1][2], a[1][3], b0, b1);
            }
        }
    }

    // ---- write partials ----
    const size_t unit = ((size_t)(b * QT2 + qt) * NCH + c);
    if (tig == 0) {
#pragma unroll
        for (int t = 0; t < 2; t++) {
            g_pm[unit * BM2 + wr0 + t * 16 + gid] = m[t][0];
            g_pm[unit * BM2 + wr0 + t * 16 + gid + 8] = m[t][1];
            g_pl[unit * BM2 + wr0 + t * 16 + gid] = l[t][0];
            g_pl[unit * BM2 + wr0 + t * 16 + gid + 8] = l[t][1];
        }
    }
    float* po = g_po + unit * BM2 * KD;
#pragma unroll
    for (int t = 0; t < 2; t++) {
        int rA = wr0 + t * 16 + gid;
#pragma unroll
        for (int nt = 0; nt < 8; nt++) {
            int col = nt * 8 + 2 * tig;
            *(float2*)&po[(size_t)rA * KD + col] = make_float2(o[t][nt][0], o[t][nt][1]);
            *(float2*)&po[(size_t)(rA + 8) * KD + col] = make_float2(o[t][nt][2], o[t][nt][3]);
        }
    }
}

// ------------------------- merge + x copy -> out ----------------------------
// block (16,16): tx -> 4 dims (float4), ty -> query; also copies x row.
__global__ __launch_bounds__(256) void merge_kernel(float* __restrict__ out,
                                                    const float4* __restrict__ x4) {
    const int tx = threadIdx.x;
    const int q = blockIdx.x * 16 + threadIdx.y;

    // copy x -> out[:, :512]
    float4* out4 = (float4*)out;
#pragma unroll
    for (int k = 0; k < 8; k++)
        out4[(size_t)q * (OUTC / 4) + tx + k * 16] = x4[(size_t)q * (CC / 4) + tx + k * 16];

    const int b = q / TT;
    const int t = q % TT;
    const int qt = t / BM2;
    const int qloc = t % BM2;
    const int nc = t / CHUNK + 1;
    const size_t base = (size_t)(b * QT2 + qt) * NCH;

    float M = -1e30f;
#pragma unroll 1
    for (int c = 0; c < nc; c++)
        M = fmaxf(M, g_pm[(base + c) * BM2 + qloc]);

    float L = 0.f;
    float4 acc = make_float4(0.f, 0.f, 0.f, 0.f);
#pragma unroll 1
    for (int c = 0; c < nc; c++) {
        float w = ex2f(g_pm[(base + c) * BM2 + qloc] - M);
        L += w * g_pl[(base + c) * BM2 + qloc];
        float4 p = *(const float4*)&g_po[((base + c) * BM2 + qloc) * KD + tx * 4];
        acc.x += w * p.x; acc.y += w * p.y;
        acc.z += w * p.z; acc.w += w * p.w;
    }
    float inv = 1.0f / L;
    *(float4*)&out[(size_t)q * OUTC + CC + tx * 4] =
        make_float4(acc.x * inv, acc.y * inv, acc.z * inv, acc.w * inv);
}

// ------------------------- launch -------------------------------------------
extern "C" void kernel_launch(void* const* d_in, const int* in_sizes, int n_in,
                              void* d_out, int out_size) {
    (void)in_sizes; (void)n_in; (void)out_size;
    const float* x  = (const float*)d_in[0];
    const float* Wq = (const float*)d_in[1];
    const float* bq = (const float*)d_in[2];
    const float* Wk = (const float*)d_in[3];
    const float* bk = (const float*)d_in[4];
    const float* Wv = (const float*)d_in[5];
    const float* bv = (const float*)d_in[6];
    float* out = (float*)d_out;

    const int M = NB * TT;  // 16384

    cudaFuncSetAttribute(qkv_kernel,
                         cudaFuncAttributeMaxDynamicSharedMemorySize,
                         QKV_SMEM_BYTES);

    qkv_kernel<<<dim3(M / 128, 3), 128, QKV_SMEM_BYTES>>>(x, Wq, bq, Wk, bk, Wv, bv);
    flash_partial<<<dim3(NCH, QT2, NB), 128>>>();
    merge_kernel<<<M / 16, dim3(16, 16)>>>(out, (const float4*)x);
}

// round 11
// speedup vs baseline: 14.3609x; 1.0930x over previous
#include <cuda_runtime.h>
#include <cuda_bf16.h>
#include <cstdint>

// Problem constants
#define NB 4
#define TT 4096
#define CC 512
#define KD 64
#define BM2 128          // queries per flash block
#define CHUNK 1024       // keys per flash unit (split-K)
#define QT2 (TT/BM2)     // 32
#define NCH (TT/CHUNK)   // 4
#define OUTC 576

// (1/sqrt(64)) * log2(e): softmax in exp2 domain
#define QS 0.1803368801111244f

#define SB 72            // bf16 row stride for all mma tiles

// ------------------------- scratch ------------------------------------------
__device__ __align__(16) __nv_bfloat16 g_qb[NB * TT * KD];   // [t][d], q pre-scaled
__device__ __align__(16) __nv_bfloat16 g_kb[NB * TT * KD];   // [t][d]
__device__ __align__(16) __nv_bfloat16 g_vt[NB * KD * TT];   // [d][t] transposed
__device__ float g_po[(size_t)NB * QT2 * NCH * BM2 * KD];
__device__ float g_pm[NB * QT2 * NCH * BM2];
__device__ float g_pl[NB * QT2 * NCH * BM2];

// ------------------------- helpers -----------------------------------------
__device__ __forceinline__ float ex2f(float x) {
    float r;
    asm("ex2.approx.f32 %0, %1;" : "=f"(r) : "f"(x));
    return r;
}
__device__ __forceinline__ unsigned cvt_bf2(float hi, float lo) {
    unsigned d;
    asm("cvt.rn.bf16x2.f32 %0, %1, %2;" : "=r"(d) : "f"(hi), "f"(lo));
    return d;
}
__device__ __forceinline__ void mma_bf16(float& d0, float& d1, float& d2, float& d3,
                                         unsigned a0, unsigned a1, unsigned a2, unsigned a3,
                                         unsigned b0, unsigned b1) {
    asm volatile(
        "mma.sync.aligned.m16n8k16.row.col.f32.bf16.bf16.f32 "
        "{%0,%1,%2,%3}, {%4,%5,%6,%7}, {%8,%9}, {%0,%1,%2,%3};"
        : "+f"(d0), "+f"(d1), "+f"(d2), "+f"(d3)
        : "r"(a0), "r"(a1), "r"(a2), "r"(a3), "r"(b0), "r"(b1));
}

// ------------------------- QKV projection (bf16 mma) ------------------------
// grid (128, 3); block 128 = 4 warps; tile 128 rows x 64 cols; K steps of 64.
__global__ __launch_bounds__(128) void qkv_kernel(
    const float* __restrict__ x,
    const float* __restrict__ Wq, const float* __restrict__ bq,
    const float* __restrict__ Wk, const float* __restrict__ bk,
    const float* __restrict__ Wv, const float* __restrict__ bv) {
    __shared__ __align__(16) __nv_bfloat16 xs[128 * SB];
    __shared__ __align__(16) __nv_bfloat16 ws[64 * SB];   // W^T: ws[n][k]

    const int which = blockIdx.y;
    const float* W = (which == 0) ? Wq : (which == 1) ? Wk : Wv;
    const float* bias = (which == 0) ? bq : (which == 1) ? bk : bv;
    const float scale = (which == 0) ? QS : 1.0f;

    const int row0 = blockIdx.x * 128;
    const int tid = threadIdx.x;
    const int lane = tid & 31;
    const int warp = tid >> 5;
    const int wr0 = warp * 32;
    const int gid = lane >> 2;
    const int tig = lane & 3;

    float o[2][8][4];
#pragma unroll
    for (int t = 0; t < 2; t++)
#pragma unroll
        for (int nt = 0; nt < 8; nt++)
#pragma unroll
            for (int r = 0; r < 4; r++) o[t][nt][r] = 0.f;

    const int wkk = tid & 63;
    const int whalf = tid >> 6;

    for (int ks0 = 0; ks0 < CC; ks0 += 64) {
        __syncthreads();
        // stage x tile [128 rows][64 k] fp32 -> bf16
#pragma unroll
        for (int i = 0; i < 16; i++) {
            int f = tid + i * 128;
            int row = f >> 4, c4 = (f & 15) * 4;
            float4 v = ((const float4*)x)[(size_t)(row0 + row) * (CC / 4) + (ks0 >> 2) + (f & 15)];
            uint2 pk;
            pk.x = cvt_bf2(v.y, v.x);
            pk.y = cvt_bf2(v.w, v.z);
            *(uint2*)&xs[row * SB + c4] = pk;
        }
        // stage W^T: ws[n][k] = bf16(W[ks0+k][n])
#pragma unroll
        for (int i = 0; i < 8; i++) {
            int n4 = whalf + i * 2;
            float4 wv = ((const float4*)W)[(size_t)(ks0 + wkk) * (KD / 4) + n4];
            ws[(n4 * 4 + 0) * SB + wkk] = __float2bfloat16_rn(wv.x);
            ws[(n4 * 4 + 1) * SB + wkk] = __float2bfloat16_rn(wv.y);
            ws[(n4 * 4 + 2) * SB + wkk] = __float2bfloat16_rn(wv.z);
            ws[(n4 * 4 + 3) * SB + wkk] = __float2bfloat16_rn(wv.w);
        }
        __syncthreads();

#pragma unroll
        for (int kk = 0; kk < 4; kk++) {
            const int ca = kk * 16 + 2 * tig;
            unsigned bf[8][2];
#pragma unroll
            for (int nt = 0; nt < 8; nt++) {
                bf[nt][0] = *(const unsigned*)&ws[(nt * 8 + gid) * SB + ca];
                bf[nt][1] = *(const unsigned*)&ws[(nt * 8 + gid) * SB + ca + 8];
            }
#pragma unroll
            for (int t = 0; t < 2; t++) {
                int rb = wr0 + t * 16;
                unsigned a0 = *(const unsigned*)&xs[(rb + gid) * SB + ca];
                unsigned a1 = *(const unsigned*)&xs[(rb + gid + 8) * SB + ca];
                unsigned a2 = *(const unsigned*)&xs[(rb + gid) * SB + ca + 8];
                unsigned a3 = *(const unsigned*)&xs[(rb + gid + 8) * SB + ca + 8];
#pragma unroll
                for (int nt = 0; nt < 8; nt++)
                    mma_bf16(o[t][nt][0], o[t][nt][1], o[t][nt][2], o[t][nt][3],
                             a0, a1, a2, a3, bf[nt][0], bf[nt][1]);
            }
        }
    }

    // epilogue: bias + scale -> bf16 (q/k: [t][d]; v: transposed [d][t])
#pragma unroll
    for (int t = 0; t < 2; t++) {
#pragma unroll
        for (int nt = 0; nt < 8; nt++) {
            int col = nt * 8 + 2 * tig;
            float b0 = bias[col], b1 = bias[col + 1];
            int rowA = row0 + wr0 + t * 16 + gid;
            float va0 = (o[t][nt][0] + b0) * scale;
            float va1 = (o[t][nt][1] + b1) * scale;
            float vb0 = (o[t][nt][2] + b0) * scale;
            float vb1 = (o[t][nt][3] + b1) * scale;
            if (which == 2) {
                int bb = rowA >> 12;
                int tA = rowA & 4095;
                g_vt[((size_t)(bb * KD + col)) * TT + tA]     = __float2bfloat16_rn(va0);
                g_vt[((size_t)(bb * KD + col + 1)) * TT + tA] = __float2bfloat16_rn(va1);
                g_vt[((size_t)(bb * KD + col)) * TT + tA + 8]     = __float2bfloat16_rn(vb0);
                g_vt[((size_t)(bb * KD + col + 1)) * TT + tA + 8] = __float2bfloat16_rn(vb1);
            } else {
                __nv_bfloat16* dst = (which == 0) ? g_qb : g_kb;
                *(unsigned*)&dst[(size_t)rowA * KD + col] = cvt_bf2(va1, va0);
                *(unsigned*)&dst[(size_t)(rowA + 8) * KD + col] = cvt_bf2(vb1, vb0);
            }
        }
    }
}

// ------------------------- flash partial (bf16 mma, warp-rows) --------------
// grid (NCH, QT2, NB); 128 threads = 4 warps; warp owns 32 query rows.
__global__ __launch_bounds__(128) void flash_partial() {
    __shared__ __align__(16) __nv_bfloat16 qs[128 * SB];
    __shared__ __align__(16) __nv_bfloat16 ks[64 * SB];
    __shared__ __align__(16) __nv_bfloat16 vt[64 * SB];   // [vdim][key]

    const int c = blockIdx.x;
    const int qt = blockIdx.y;
    const int b = blockIdx.z;
    const int qend = (qt + 1) * BM2;
    const int k0 = c * CHUNK;
    if (k0 >= qend) return;
    const int kend = (k0 + CHUNK < qend) ? (k0 + CHUNK) : qend;

    const int tid = threadIdx.x;
    const int lane = tid & 31;
    const int warp = tid >> 5;
    const int wr0 = warp * 32;
    const int gid = lane >> 2;
    const int tig = lane & 3;
    const int wq0 = qt * BM2 + wr0;
    const unsigned fullm = 0xffffffffu;

    // stage Q tile (once)
    {
        const uint4* qp = (const uint4*)(g_qb + ((size_t)b * TT + qt * BM2) * KD);
#pragma unroll
        for (int i = 0; i < 8; i++) {
            int f = tid + i * 128;
            int row = f >> 3, ch = f & 7;
            *(uint4*)&qs[row * SB + ch * 8] = qp[f];
        }
    }

    float o[2][8][4];
    float m[2][2], l[2][2];
#pragma unroll
    for (int t = 0; t < 2; t++) {
#pragma unroll
        for (int nt = 0; nt < 8; nt++)
#pragma unroll
            for (int r = 0; r < 4; r++) o[t][nt][r] = 0.f;
        m[t][0] = -1e30f; m[t][1] = -1e30f;
        l[t][0] = 0.f; l[t][1] = 0.f;
    }

    for (int s0 = k0; s0 < kend; s0 += 64) {
        __syncthreads();
        {
            const uint4* kp = (const uint4*)(g_kb + ((size_t)b * TT + s0) * KD);
#pragma unroll
            for (int i = 0; i < 4; i++) {
                int f = tid + i * 128;
                int row = f >> 3, ch = f & 7;
                *(uint4*)&ks[row * SB + ch * 8] = kp[f];
                *(uint4*)&vt[row * SB + ch * 8] =
                    ((const uint4*)(g_vt + ((size_t)(b * KD + row)) * TT + s0))[ch];
            }
        }
        __syncthreads();

        if (s0 > wq0 + 31) continue;

        // ---- S = Q K^T (bf16 m16n8k16) ----
        float sacc[2][8][4];
#pragma unroll
        for (int t = 0; t < 2; t++)
#pragma unroll
            for (int nt = 0; nt < 8; nt++)
#pragma unroll
                for (int r = 0; r < 4; r++) sacc[t][nt][r] = 0.f;

#pragma unroll
        for (int kk = 0; kk < 4; kk++) {
            const int ca = kk * 16 + 2 * tig;
            unsigned bf[8][2];
#pragma unroll
            for (int nt = 0; nt < 8; nt++) {
                bf[nt][0] = *(const unsigned*)&ks[(nt * 8 + gid) * SB + ca];
                bf[nt][1] = *(const unsigned*)&ks[(nt * 8 + gid) * SB + ca + 8];
            }
#pragma unroll
            for (int t = 0; t < 2; t++) {
                int rb = wr0 + t * 16;
                unsigned a0 = *(const unsigned*)&qs[(rb + gid) * SB + ca];
                unsigned a1 = *(const unsigned*)&qs[(rb + gid + 8) * SB + ca];
                unsigned a2 = *(const unsigned*)&qs[(rb + gid) * SB + ca + 8];
                unsigned a3 = *(const unsigned*)&qs[(rb + gid + 8) * SB + ca + 8];
#pragma unroll
                for (int nt = 0; nt < 8; nt++)
                    mma_bf16(sacc[t][nt][0], sacc[t][nt][1], sacc[t][nt][2], sacc[t][nt][3],
                             a0, a1, a2, a3, bf[nt][0], bf[nt][1]);
            }
        }

        // ---- causal mask ----
        if (s0 + 63 > wq0) {
#pragma unroll
            for (int t = 0; t < 2; t++) {
                int rq0 = wq0 + t * 16 + gid;
                int rq1 = rq0 + 8;
#pragma unroll
                for (int nt = 0; nt < 8; nt++) {
                    int ck = s0 + nt * 8 + 2 * tig;
                    if (ck > rq0) sacc[t][nt][0] = -1e30f;
                    if (ck + 1 > rq0) sacc[t][nt][1] = -1e30f;
                    if (ck > rq1) sacc[t][nt][2] = -1e30f;
                    if (ck + 1 > rq1) sacc[t][nt][3] = -1e30f;
                }
            }
        }

        // ---- warp-local online softmax ----
#pragma unroll
        for (int t = 0; t < 2; t++) {
            float mx0 = -1e30f, mx1 = -1e30f;
#pragma unroll
            for (int nt = 0; nt < 8; nt++) {
                mx0 = fmaxf(mx0, fmaxf(sacc[t][nt][0], sacc[t][nt][1]));
                mx1 = fmaxf(mx1, fmaxf(sacc[t][nt][2], sacc[t][nt][3]));
            }
            mx0 = fmaxf(mx0, __shfl_xor_sync(fullm, mx0, 1));
            mx0 = fmaxf(mx0, __shfl_xor_sync(fullm, mx0, 2));
            mx1 = fmaxf(mx1, __shfl_xor_sync(fullm, mx1, 1));
            mx1 = fmaxf(mx1, __shfl_xor_sync(fullm, mx1, 2));
            float mn0 = fmaxf(m[t][0], mx0);
            float mn1 = fmaxf(m[t][1], mx1);
            float corr0 = ex2f(m[t][0] - mn0);
            float corr1 = ex2f(m[t][1] - mn1);
            m[t][0] = mn0; m[t][1] = mn1;
            float sum0 = 0.f, sum1 = 0.f;
#pragma unroll
            for (int nt = 0; nt < 8; nt++) {
                sacc[t][nt][0] = ex2f(sacc[t][nt][0] - mn0);
                sacc[t][nt][1] = ex2f(sacc[t][nt][1] - mn0);
                sacc[t][nt][2] = ex2f(sacc[t][nt][2] - mn1);
                sacc[t][nt][3] = ex2f(sacc[t][nt][3] - mn1);
                sum0 += sacc[t][nt][0] + sacc[t][nt][1];
                sum1 += sacc[t][nt][2] + sacc[t][nt][3];
            }
            sum0 += __shfl_xor_sync(fullm, sum0, 1);
            sum0 += __shfl_xor_sync(fullm, sum0, 2);
            sum1 += __shfl_xor_sync(fullm, sum1, 1);
            sum1 += __shfl_xor_sync(fullm, sum1, 2);
            l[t][0] = l[t][0] * corr0 + sum0;
            l[t][1] = l[t][1] * corr1 + sum1;
#pragma unroll
            for (int nt = 0; nt < 8; nt++) {
                o[t][nt][0] *= corr0; o[t][nt][1] *= corr0;
                o[t][nt][2] *= corr1; o[t][nt][3] *= corr1;
            }
        }

        // ---- O += P V: C-frag == A-frag layout for k16 -> just cvt ----
#pragma unroll
        for (int kk = 0; kk < 4; kk++) {
            unsigned a[2][4];
#pragma unroll
            for (int t = 0; t < 2; t++) {
                a[t][0] = cvt_bf2(sacc[t][2 * kk][1], sacc[t][2 * kk][0]);
                a[t][1] = cvt_bf2(sacc[t][2 * kk][3], sacc[t][2 * kk][2]);
                a[t][2] = cvt_bf2(sacc[t][2 * kk + 1][1], sacc[t][2 * kk + 1][0]);
                a[t][3] = cvt_bf2(sacc[t][2 * kk + 1][3], sacc[t][2 * kk + 1][2]);
            }
            const int kb = kk * 16 + 2 * tig;
#pragma unroll
            for (int nt = 0; nt < 8; nt++) {
                int vc = nt * 8 + gid;
                unsigned b0 = *(const unsigned*)&vt[vc * SB + kb];
                unsigned b1 = *(const unsigned*)&vt[vc * SB + kb + 8];
                mma_bf16(o[0][nt][0], o[0][nt][1], o[0][nt][2], o[0][nt][3],
                         a[0][0], a[0][1], a[0][2], a[0][3], b0, b1);
                mma_bf16(o[1][nt][0], o[1][nt][1], o[1][nt][2], o[1][nt][3],
                         a[1][0], a[1][1], a[1][2], a[1][3], b0, b1);
            }
        }
    }

    // ---- write partials ----
    const size_t unit = ((size_t)(b * QT2 + qt) * NCH + c);
    if (tig == 0) {
#pragma unroll
        for (int t = 0; t < 2; t++) {
            g_pm[unit * BM2 + wr0 + t * 16 + gid] = m[t][0];
            g_pm[unit * BM2 + wr0 + t * 16 + gid + 8] = m[t][1];
            g_pl[unit * BM2 + wr0 + t * 16 + gid] = l[t][0];
            g_pl[unit * BM2 + wr0 + t * 16 + gid + 8] = l[t][1];
        }
    }
    float* po = g_po + unit * BM2 * KD;
#pragma unroll
    for (int t = 0; t < 2; t++) {
        int rA = wr0 + t * 16 + gid;
#pragma unroll
        for (int nt = 0; nt < 8; nt++) {
            int col = nt * 8 + 2 * tig;
            *(float2*)&po[(size_t)rA * KD + col] = make_float2(o[t][nt][0], o[t][nt][1]);
            *(float2*)&po[(size_t)(rA + 8) * KD + col] = make_float2(o[t][nt][2], o[t][nt][3]);
        }
    }
}

// ------------------------- merge + x copy -> out ----------------------------
// block (16,16): tx -> 4 dims (float4), ty -> query; also copies x row.
__global__ __launch_bounds__(256) void merge_kernel(float* __restrict__ out,
                                                    const float4* __restrict__ x4) {
    const int tx = threadIdx.x;
    const int q = blockIdx.x * 16 + threadIdx.y;

    // copy x -> out[:, :512]
    float4* out4 = (float4*)out;
#pragma unroll
    for (int k = 0; k < 8; k++)
        out4[(size_t)q * (OUTC / 4) + tx + k * 16] = x4[(size_t)q * (CC / 4) + tx + k * 16];

    const int b = q / TT;
    const int t = q % TT;
    const int qt = t / BM2;
    const int qloc = t % BM2;
    const int nc = t / CHUNK + 1;
    const size_t base = (size_t)(b * QT2 + qt) * NCH;

    float M = -1e30f;
#pragma unroll 1
    for (int c = 0; c < nc; c++)
        M = fmaxf(M, g_pm[(base + c) * BM2 + qloc]);

    float L = 0.f;
    float4 acc = make_float4(0.f, 0.f, 0.f, 0.f);
#pragma unroll 1
    for (int c = 0; c < nc; c++) {
        float w = ex2f(g_pm[(base + c) * BM2 + qloc] - M);
        L += w * g_pl[(base + c) * BM2 + qloc];
        float4 p = *(const float4*)&g_po[((base + c) * BM2 + qloc) * KD + tx * 4];
        acc.x += w * p.x; acc.y += w * p.y;
        acc.z += w * p.z; acc.w += w * p.w;
    }
    float inv = 1.0f / L;
    *(float4*)&out[(size_t)q * OUTC + CC + tx * 4] =
        make_float4(acc.x * inv, acc.y * inv, acc.z * inv, acc.w * inv);
}

// ------------------------- launch -------------------------------------------
extern "C" void kernel_launch(void* const* d_in, const int* in_sizes, int n_in,
                              void* d_out, int out_size) {
    (void)in_sizes; (void)n_in; (void)out_size;
    const float* x  = (const float*)d_in[0];
    const float* Wq = (const float*)d_in[1];
    const float* bq = (const float*)d_in[2];
    const float* Wk = (const float*)d_in[3];
    const float* bk = (const float*)d_in[4];
    const float* Wv = (const float*)d_in[5];
    const float* bv = (const float*)d_in[6];
    float* out = (float*)d_out;

    const int M = NB * TT;  // 16384

    qkv_kernel<<<dim3(M / 128, 3), 128>>>(x, Wq, bq, Wk, bk, Wv, bv);
    flash_partial<<<dim3(NCH, QT2, NB), 128>>>();
    merge_kernel<<<M / 16, dim3(16, 16)>>>(out, (const float4*)x);
}

// round 12
// speedup vs baseline: 16.0608x; 1.1184x over previous
#include <cuda_runtime.h>
#include <cuda_bf16.h>
#include <cstdint>

typedef __nv_bfloat16 bf16;

// Problem constants
#define NB 4
#define TT 4096
#define CC 512
#define KD 64
#define BM2 128          // queries per flash block
#define CHUNK 1024       // keys per flash unit (split-K)
#define QT2 (TT/BM2)     // 32
#define NCH (TT/CHUNK)   // 4
#define OUTC 576

// (1/sqrt(64)) * log2(e): softmax in exp2 domain
#define QS 0.1803368801111244f

#define SB 72            // bf16 row stride for all mma tiles (144B: conflict-free)

#define PIPE_SMEM_BYTES 55296   // both big kernels use 27648 bf16 = 54KB

// ------------------------- scratch ------------------------------------------
__device__ __align__(16) bf16 g_xb[NB * TT * CC];    // x as bf16 [t][c]   16MB
__device__ __align__(16) bf16 g_wt[3 * KD * CC];     // W^T bf16 [which][n][k]
__device__ __align__(16) bf16 g_qb[NB * TT * KD];    // [t][d], q pre-scaled
__device__ __align__(16) bf16 g_kb[NB * TT * KD];    // [t][d]
__device__ __align__(16) bf16 g_vt[NB * KD * TT];    // [d][t] transposed
__device__ float g_po[(size_t)NB * QT2 * NCH * BM2 * KD];
__device__ float g_pm[NB * QT2 * NCH * BM2];
__device__ float g_pl[NB * QT2 * NCH * BM2];

// ------------------------- helpers -----------------------------------------
__device__ __forceinline__ float ex2f(float x) {
    float r;
    asm("ex2.approx.f32 %0, %1;" : "=f"(r) : "f"(x));
    return r;
}
__device__ __forceinline__ unsigned cvt_bf2(float hi, float lo) {
    unsigned d;
    asm("cvt.rn.bf16x2.f32 %0, %1, %2;" : "=r"(d) : "f"(hi), "f"(lo));
    return d;
}
__device__ __forceinline__ void mma_bf16(float& d0, float& d1, float& d2, float& d3,
                                         unsigned a0, unsigned a1, unsigned a2, unsigned a3,
                                         unsigned b0, unsigned b1) {
    asm volatile(
        "mma.sync.aligned.m16n8k16.row.col.f32.bf16.bf16.f32 "
        "{%0,%1,%2,%3}, {%4,%5,%6,%7}, {%8,%9}, {%0,%1,%2,%3};"
        : "+f"(d0), "+f"(d1), "+f"(d2), "+f"(d3)
        : "r"(a0), "r"(a1), "r"(a2), "r"(a3), "r"(b0), "r"(b1));
}
__device__ __forceinline__ unsigned smem_u32(const void* p) {
    return (unsigned)__cvta_generic_to_shared(p);
}
__device__ __forceinline__ void cp16(unsigned s, const void* g) {
    asm volatile("cp.async.cg.shared.global [%0], [%1], 16;" :: "r"(s), "l"(g));
}
__device__ __forceinline__ void ldm4(unsigned& r0, unsigned& r1, unsigned& r2, unsigned& r3,
                                     const bf16* p) {
    unsigned a = smem_u32(p);
    asm volatile("ldmatrix.sync.aligned.m8n8.x4.shared.b16 {%0,%1,%2,%3}, [%4];"
                 : "=r"(r0), "=r"(r1), "=r"(r2), "=r"(r3) : "r"(a));
}

// ------------------------- prep: x -> bf16 ----------------------------------
__global__ __launch_bounds__(256) void xconv_kernel(const float4* __restrict__ x4) {
    int i = blockIdx.x * 256 + threadIdx.x;     // 0..524287
#pragma unroll
    for (int j = 0; j < 4; j++) {
        int idx = i + j * 524288;               // 2M float4 total
        float4 v = x4[idx];
        uint2 p;
        p.x = cvt_bf2(v.y, v.x);
        p.y = cvt_bf2(v.w, v.z);
        ((uint2*)g_xb)[idx] = p;
    }
}

// ------------------------- prep: W -> bf16 transposed ------------------------
__global__ __launch_bounds__(256) void wconv_kernel(const float* __restrict__ Wq,
                                                    const float* __restrict__ Wk,
                                                    const float* __restrict__ Wv) {
    const int which = blockIdx.x;
    const float* W = (which == 0) ? Wq : (which == 1) ? Wk : Wv;
    bf16* dst = g_wt + which * KD * CC;
    const int kb = blockIdx.y * 16;
#pragma unroll
    for (int i = 0; i < 4; i++) {
        int e = threadIdx.x + i * 256;          // 0..1023 over 16k x 64n
        int k = kb + (e >> 6);
        int n = e & 63;
        dst[n * CC + k] = __float2bfloat16_rn(W[(size_t)k * KD + n]);
    }
}

// ------------------------- QKV projection (bf16 mma, cp.async pipe) ---------
// grid (128, 3); block 128 = 4 warps; tile 128 rows x 64 cols; K steps of 64.
#define QKV_STAGE(buf, ks0) do {                                                  \
    _Pragma("unroll") for (int i_ = 0; i_ < 8; i_++) {                            \
        int f_ = tid + i_ * 128, row_ = f_ >> 3, ch_ = f_ & 7;                    \
        cp16(smem_u32(&xs[buf][row_ * SB + ch_ * 8]),                             \
             xb + (size_t)row_ * CC + (ks0) + ch_ * 8);                           \
    }                                                                             \
    _Pragma("unroll") for (int i_ = 0; i_ < 4; i_++) {                            \
        int f_ = tid + i_ * 128, row_ = f_ >> 3, ch_ = f_ & 7;                    \
        cp16(smem_u32(&ws[buf][row_ * SB + ch_ * 8]),                             \
             wt + (size_t)row_ * CC + (ks0) + ch_ * 8);                           \
    }                                                                             \
    asm volatile("cp.async.commit_group;");                                       \
} while (0)

__global__ __launch_bounds__(128) void qkv_kernel(const float* __restrict__ bq,
                                                  const float* __restrict__ bk,
                                                  const float* __restrict__ bv) {
    extern __shared__ bf16 smem[];
    bf16* xs[2] = { smem, smem + 128 * SB };
    bf16* ws[2] = { smem + 2 * 128 * SB, smem + 2 * 128 * SB + 64 * SB };

    const int which = blockIdx.y;
    const float* bias = (which == 0) ? bq : (which == 1) ? bk : bv;
    const float scale = (which == 0) ? QS : 1.0f;

    const int row0 = blockIdx.x * 128;
    const bf16* xb = g_xb + (size_t)row0 * CC;
    const bf16* wt = g_wt + which * KD * CC;

    const int tid = threadIdx.x;
    const int lane = tid & 31;
    const int warp = tid >> 5;
    const int wr0 = warp * 32;
    const int gid = lane >> 2;
    const int tig = lane & 3;
    const int r8 = lane & 7;
    const int sel = lane >> 3;
    const int sel01 = sel & 1;
    const int sel2 = sel >> 1;

    float o[2][8][4];
#pragma unroll
    for (int t = 0; t < 2; t++)
#pragma unroll
        for (int nt = 0; nt < 8; nt++)
#pragma unroll
            for (int r = 0; r < 4; r++) o[t][nt][r] = 0.f;

    QKV_STAGE(0, 0);

    for (int step = 0; step < 8; step++) {
        asm volatile("cp.async.wait_group 0;");
        __syncthreads();
        if (step < 7) QKV_STAGE((step + 1) & 1, (step + 1) * 64);

        const bf16* X = xs[step & 1];
        const bf16* W2 = ws[step & 1];
#pragma unroll
        for (int kk = 0; kk < 4; kk++) {
            const int cb = kk * 16;
            unsigned bfr[8][2];
#pragma unroll
            for (int np = 0; np < 4; np++)
                ldm4(bfr[2 * np][0], bfr[2 * np][1], bfr[2 * np + 1][0], bfr[2 * np + 1][1],
                     &W2[(np * 16 + r8 + sel2 * 8) * SB + cb + sel01 * 8]);
#pragma unroll
            for (int t = 0; t < 2; t++) {
                unsigned a0, a1, a2, a3;
                ldm4(a0, a1, a2, a3,
                     &X[(wr0 + t * 16 + r8 + sel01 * 8) * SB + cb + sel2 * 8]);
#pragma unroll
                for (int nt = 0; nt < 8; nt++)
                    mma_bf16(o[t][nt][0], o[t][nt][1], o[t][nt][2], o[t][nt][3],
                             a0, a1, a2, a3, bfr[nt][0], bfr[nt][1]);
            }
        }
    }

    // epilogue: bias + scale -> bf16 (q/k: [t][d]; v: transposed [d][t])
#pragma unroll
    for (int t = 0; t < 2; t++) {
#pragma unroll
        for (int nt = 0; nt < 8; nt++) {
            int col = nt * 8 + 2 * tig;
            float b0 = bias[col], b1 = bias[col + 1];
            int rowA = row0 + wr0 + t * 16 + gid;
            float va0 = (o[t][nt][0] + b0) * scale;
            float va1 = (o[t][nt][1] + b1) * scale;
            float vb0 = (o[t][nt][2] + b0) * scale;
            float vb1 = (o[t][nt][3] + b1) * scale;
            if (which == 2) {
                int bb = rowA >> 12;
                int tA = rowA & 4095;
                g_vt[((size_t)(bb * KD + col)) * TT + tA]         = __float2bfloat16_rn(va0);
                g_vt[((size_t)(bb * KD + col + 1)) * TT + tA]     = __float2bfloat16_rn(va1);
                g_vt[((size_t)(bb * KD + col)) * TT + tA + 8]     = __float2bfloat16_rn(vb0);
                g_vt[((size_t)(bb * KD + col + 1)) * TT + tA + 8] = __float2bfloat16_rn(vb1);
            } else {
                bf16* dst = (which == 0) ? g_qb : g_kb;
                *(unsigned*)&dst[(size_t)rowA * KD + col] = cvt_bf2(va1, va0);
                *(unsigned*)&dst[(size_t)(rowA + 8) * KD + col] = cvt_bf2(vb1, vb0);
            }
        }
    }
}

// ------------------------- flash partial (bf16 mma, cp.async pipe) ----------
// grid (NCH, QT2, NB); 128 threads = 4 warps; warp owns 32 query rows.
#define KV_STAGE(buf, s0) do {                                                    \
    _Pragma("unroll") for (int i_ = 0; i_ < 4; i_++) {                            \
        int f_ = tid + i_ * 128, row_ = f_ >> 3, ch_ = f_ & 7;                    \
        cp16(smem_u32(&ksb[buf][row_ * SB + ch_ * 8]),                            \
             g_kb + ((size_t)b * TT + (s0) + row_) * KD + ch_ * 8);               \
        cp16(smem_u32(&vtb[buf][row_ * SB + ch_ * 8]),                            \
             g_vt + ((size_t)(b * KD + row_)) * TT + (s0) + ch_ * 8);             \
    }                                                                             \
    asm volatile("cp.async.commit_group;");                                       \
} while (0)

__global__ __launch_bounds__(128) void flash_partial() {
    extern __shared__ bf16 smem[];
    bf16* qs = smem;                                       // [128][SB]
    bf16* ksb[2] = { smem + 128 * SB, smem + 128 * SB + 64 * SB };
    bf16* vtb[2] = { smem + 256 * SB, smem + 256 * SB + 64 * SB };

    const int c = blockIdx.x;
    const int qt = blockIdx.y;
    const int b = blockIdx.z;
    const int qend = (qt + 1) * BM2;
    const int k0 = c * CHUNK;
    if (k0 >= qend) return;
    const int kend = (k0 + CHUNK < qend) ? (k0 + CHUNK) : qend;

    const int tid = threadIdx.x;
    const int lane = tid & 31;
    const int warp = tid >> 5;
    const int wr0 = warp * 32;
    const int gid = lane >> 2;
    const int tig = lane & 3;
    const int r8 = lane & 7;
    const int sel = lane >> 3;
    const int sel01 = sel & 1;
    const int sel2 = sel >> 1;
    const int wq0 = qt * BM2 + wr0;
    const unsigned fullm = 0xffffffffu;

    KV_STAGE(0, k0);

    // stage Q tile (once)
    {
        const uint4* qp = (const uint4*)(g_qb + ((size_t)b * TT + qt * BM2) * KD);
#pragma unroll
        for (int i = 0; i < 8; i++) {
            int f = tid + i * 128;
            int row = f >> 3, ch = f & 7;
            *(uint4*)&qs[row * SB + ch * 8] = qp[f];
        }
    }

    float o[2][8][4];
    float m[2][2], l[2][2];
#pragma unroll
    for (int t = 0; t < 2; t++) {
#pragma unroll
        for (int nt = 0; nt < 8; nt++)
#pragma unroll
            for (int r = 0; r < 4; r++) o[t][nt][r] = 0.f;
        m[t][0] = -1e30f; m[t][1] = -1e30f;
        l[t][0] = 0.f; l[t][1] = 0.f;
    }

    const int nsub = (kend - k0) >> 6;
    for (int i = 0; i < nsub; i++) {
        const int s0 = k0 + i * 64;
        asm volatile("cp.async.wait_group 0;");
        __syncthreads();
        if (i + 1 < nsub) KV_STAGE((i + 1) & 1, s0 + 64);

        if (s0 <= wq0 + 31) {
            const bf16* K2 = ksb[i & 1];
            const bf16* V2 = vtb[i & 1];

            // ---- S = Q K^T ----
            float sacc[2][8][4];
#pragma unroll
            for (int t = 0; t < 2; t++)
#pragma unroll
                for (int nt = 0; nt < 8; nt++)
#pragma unroll
                    for (int r = 0; r < 4; r++) sacc[t][nt][r] = 0.f;

#pragma unroll
            for (int kk = 0; kk < 4; kk++) {
                const int cb = kk * 16;
                unsigned bfr[8][2];
#pragma unroll
                for (int np = 0; np < 4; np++)
                    ldm4(bfr[2 * np][0], bfr[2 * np][1], bfr[2 * np + 1][0], bfr[2 * np + 1][1],
                         &K2[(np * 16 + r8 + sel2 * 8) * SB + cb + sel01 * 8]);
#pragma unroll
                for (int t = 0; t < 2; t++) {
                    unsigned a0, a1, a2, a3;
                    ldm4(a0, a1, a2, a3,
                         &qs[(wr0 + t * 16 + r8 + sel01 * 8) * SB + cb + sel2 * 8]);
#pragma unroll
                    for (int nt = 0; nt < 8; nt++)
                        mma_bf16(sacc[t][nt][0], sacc[t][nt][1], sacc[t][nt][2], sacc[t][nt][3],
                                 a0, a1, a2, a3, bfr[nt][0], bfr[nt][1]);
                }
            }

            // ---- causal mask ----
            if (s0 + 63 > wq0) {
#pragma unroll
                for (int t = 0; t < 2; t++) {
                    int rq0 = wq0 + t * 16 + gid;
                    int rq1 = rq0 + 8;
#pragma unroll
                    for (int nt = 0; nt < 8; nt++) {
                        int ck = s0 + nt * 8 + 2 * tig;
                        if (ck > rq0) sacc[t][nt][0] = -1e30f;
                        if (ck + 1 > rq0) sacc[t][nt][1] = -1e30f;
                        if (ck > rq1) sacc[t][nt][2] = -1e30f;
                        if (ck + 1 > rq1) sacc[t][nt][3] = -1e30f;
                    }
                }
            }

            // ---- warp-local online softmax ----
#pragma unroll
            for (int t = 0; t < 2; t++) {
                float mx0 = -1e30f, mx1 = -1e30f;
#pragma unroll
                for (int nt = 0; nt < 8; nt++) {
                    mx0 = fmaxf(mx0, fmaxf(sacc[t][nt][0], sacc[t][nt][1]));
                    mx1 = fmaxf(mx1, fmaxf(sacc[t][nt][2], sacc[t][nt][3]));
                }
                mx0 = fmaxf(mx0, __shfl_xor_sync(fullm, mx0, 1));
                mx0 = fmaxf(mx0, __shfl_xor_sync(fullm, mx0, 2));
                mx1 = fmaxf(mx1, __shfl_xor_sync(fullm, mx1, 1));
                mx1 = fmaxf(mx1, __shfl_xor_sync(fullm, mx1, 2));
                float mn0 = fmaxf(m[t][0], mx0);
                float mn1 = fmaxf(m[t][1], mx1);
                float corr0 = ex2f(m[t][0] - mn0);
                float corr1 = ex2f(m[t][1] - mn1);
                m[t][0] = mn0; m[t][1] = mn1;
                float sum0 = 0.f, sum1 = 0.f;
#pragma unroll
                for (int nt = 0; nt < 8; nt++) {
                    sacc[t][nt][0] = ex2f(sacc[t][nt][0] - mn0);
                    sacc[t][nt][1] = ex2f(sacc[t][nt][1] - mn0);
                    sacc[t][nt][2] = ex2f(sacc[t][nt][2] - mn1);
                    sacc[t][nt][3] = ex2f(sacc[t][nt][3] - mn1);
                    sum0 += sacc[t][nt][0] + sacc[t][nt][1];
                    sum1 += sacc[t][nt][2] + sacc[t][nt][3];
                }
                sum0 += __shfl_xor_sync(fullm, sum0, 1);
                sum0 += __shfl_xor_sync(fullm, sum0, 2);
                sum1 += __shfl_xor_sync(fullm, sum1, 1);
                sum1 += __shfl_xor_sync(fullm, sum1, 2);
                l[t][0] = l[t][0] * corr0 + sum0;
                l[t][1] = l[t][1] * corr1 + sum1;
#pragma unroll
                for (int nt = 0; nt < 8; nt++) {
                    o[t][nt][0] *= corr0; o[t][nt][1] *= corr0;
                    o[t][nt][2] *= corr1; o[t][nt][3] *= corr1;
                }
            }

            // ---- O += P V: C-frag == A-frag layout for k16 -> just cvt ----
#pragma unroll
            for (int kk = 0; kk < 4; kk++) {
                unsigned a[2][4];
#pragma unroll
                for (int t = 0; t < 2; t++) {
                    a[t][0] = cvt_bf2(sacc[t][2 * kk][1], sacc[t][2 * kk][0]);
                    a[t][1] = cvt_bf2(sacc[t][2 * kk][3], sacc[t][2 * kk][2]);
                    a[t][2] = cvt_bf2(sacc[t][2 * kk + 1][1], sacc[t][2 * kk + 1][0]);
                    a[t][3] = cvt_bf2(sacc[t][2 * kk + 1][3], sacc[t][2 * kk + 1][2]);
                }
                const int cb = kk * 16;
                unsigned bfr[8][2];
#pragma unroll
                for (int np = 0; np < 4; np++)
                    ldm4(bfr[2 * np][0], bfr[2 * np][1], bfr[2 * np + 1][0], bfr[2 * np + 1][1],
                         &V2[(np * 16 + r8 + sel2 * 8) * SB + cb + sel01 * 8]);
#pragma unroll
                for (int nt = 0; nt < 8; nt++) {
                    mma_bf16(o[0][nt][0], o[0][nt][1], o[0][nt][2], o[0][nt][3],
                             a[0][0], a[0][1], a[0][2], a[0][3], bfr[nt][0], bfr[nt][1]);
                    mma_bf16(o[1][nt][0], o[1][nt][1], o[1][nt][2], o[1][nt][3],
                             a[1][0], a[1][1], a[1][2], a[1][3], bfr[nt][0], bfr[nt][1]);
                }
            }
        }
    }

    // ---- write partials ----
    const size_t unit = ((size_t)(b * QT2 + qt) * NCH + c);
    if (tig == 0) {
#pragma unroll
        for (int t = 0; t < 2; t++) {
            g_pm[unit * BM2 + wr0 + t * 16 + gid] = m[t][0];
            g_pm[unit * BM2 + wr0 + t * 16 + gid + 8] = m[t][1];
            g_pl[unit * BM2 + wr0 + t * 16 + gid] = l[t][0];
            g_pl[unit * BM2 + wr0 + t * 16 + gid + 8] = l[t][1];
        }
    }
    float* po = g_po + unit * BM2 * KD;
#pragma unroll
    for (int t = 0; t < 2; t++) {
        int rA = wr0 + t * 16 + gid;
#pragma unroll
        for (int nt = 0; nt < 8; nt++) {
            int col = nt * 8 + 2 * tig;
            *(float2*)&po[(size_t)rA * KD + col] = make_float2(o[t][nt][0], o[t][nt][1]);
            *(float2*)&po[(size_t)(rA + 8) * KD + col] = make_float2(o[t][nt][2], o[t][nt][3]);
        }
    }
}

// ------------------------- merge + x copy -> out ----------------------------
__global__ __launch_bounds__(256) void merge_kernel(float* __restrict__ out,
                                                    const float4* __restrict__ x4) {
    const int tx = threadIdx.x;
    const int q = blockIdx.x * 16 + threadIdx.y;

    float4* out4 = (float4*)out;
#pragma unroll
    for (int k = 0; k < 8; k++)
        out4[(size_t)q * (OUTC / 4) + tx + k * 16] = x4[(size_t)q * (CC / 4) + tx + k * 16];

    const int b = q / TT;
    const int t = q % TT;
    const int qt = t / BM2;
    const int qloc = t % BM2;
    const int nc = t / CHUNK + 1;
    const size_t base = (size_t)(b * QT2 + qt) * NCH;

    float M = -1e30f;
#pragma unroll 1
    for (int c = 0; c < nc; c++)
        M = fmaxf(M, g_pm[(base + c) * BM2 + qloc]);

    float L = 0.f;
    float4 acc = make_float4(0.f, 0.f, 0.f, 0.f);
#pragma unroll 1
    for (int c = 0; c < nc; c++) {
        float w = ex2f(g_pm[(base + c) * BM2 + qloc] - M);
        L += w * g_pl[(base + c) * BM2 + qloc];
        float4 p = *(const float4*)&g_po[((base + c) * BM2 + qloc) * KD + tx * 4];
        acc.x += w * p.x; acc.y += w * p.y;
        acc.z += w * p.z; acc.w += w * p.w;
    }
    float inv = 1.0f / L;
    *(float4*)&out[(size_t)q * OUTC + CC + tx * 4] =
        make_float4(acc.x * inv, acc.y * inv, acc.z * inv, acc.w * inv);
}

// ------------------------- launch -------------------------------------------
extern "C" void kernel_launch(void* const* d_in, const int* in_sizes, int n_in,
                              void* d_out, int out_size) {
    (void)in_sizes; (void)n_in; (void)out_size;
    const float* x  = (const float*)d_in[0];
    const float* Wq = (const float*)d_in[1];
    const float* bq = (const float*)d_in[2];
    const float* Wk = (const float*)d_in[3];
    const float* bk = (const float*)d_in[4];
    const float* Wv = (const float*)d_in[5];
    const float* bv = (const float*)d_in[6];
    float* out = (float*)d_out;

    const int M = NB * TT;  // 16384

    cudaFuncSetAttribute(qkv_kernel,
                         cudaFuncAttributeMaxDynamicSharedMemorySize, PIPE_SMEM_BYTES);
    cudaFuncSetAttribute(flash_partial,
                         cudaFuncAttributeMaxDynamicSharedMemorySize, PIPE_SMEM_BYTES);

    xconv_kernel<<<2048, 256>>>((const float4*)x);
    wconv_kernel<<<dim3(3, 32), 256>>>(Wq, Wk, Wv);
    qkv_kernel<<<dim3(M / 128, 3), 128, PIPE_SMEM_BYTES>>>(bq, bk, bv);
    flash_partial<<<dim3(NCH, QT2, NB), 128, PIPE_SMEM_BYTES>>>();
    merge_kernel<<<M / 16, dim3(16, 16)>>>(out, (const float4*)x);
}